// round 1
// baseline (speedup 1.0000x reference)
#include <cuda_runtime.h>
#include <cstdint>

#define N_ENT   30000
#define N_RELS  12
#define N_BASES 8
#define KGD     128
#define TOKD    768
#define BATCH   32
#define NCTX    50
#define SEQL    256
#define NEDGE   400000

// ---------------- scratch (__device__ globals; no allocations allowed) ----
__device__ float g_weight[N_RELS * N_ENT * KGD];   // 184 MB: composed per-rel weights
__device__ float g_kg[N_ENT * KGD];                 // agg -> kg_embedding (in place)
__device__ int   g_cnt[N_RELS * N_ENT];             // per (rel,dst) edge counts
__device__ float g_e_tok[BATCH * SEQL];             // token attention logits
__device__ float g_ent_rep[BATCH * KGD];            // entity_attn_rep
__device__ float g_user[BATCH * KGD];               // user embedding

// ---------------- 0: zero scratch ----------------------------------------
__global__ void zero_kernel() {
    int i = blockIdx.x * blockDim.x + threadIdx.x;
    int stride = gridDim.x * blockDim.x;
    for (int j = i; j < N_ENT * KGD; j += stride) g_kg[j] = 0.f;
    for (int j = i; j < N_RELS * N_ENT; j += stride) g_cnt[j] = 0;
    for (int j = i; j < BATCH * SEQL; j += stride) g_e_tok[j] = 0.f;
}

// ---------------- 1: weight[r,n,d] = sum_b comp[r,b]*basis[b,n,d] --------
// float4 over the (n,d) plane: 960000 float4s; 8 reads, 12 writes each.
__global__ void weight_kernel(const float* __restrict__ comp,
                              const float* __restrict__ basis) {
    __shared__ float c[N_RELS * N_BASES];
    int tid = threadIdx.x;
    if (tid < N_RELS * N_BASES) c[tid] = comp[tid];
    __syncthreads();

    int i = blockIdx.x * blockDim.x + tid;   // [0, 960000)
    const int NM4 = (N_ENT * KGD) / 4;       // 960000
    if (i >= NM4) return;

    float4 bv[N_BASES];
    const float4* b4 = (const float4*)basis;
#pragma unroll
    for (int b = 0; b < N_BASES; b++) bv[b] = b4[(size_t)b * NM4 + i];

    float4* w4 = (float4*)g_weight;
#pragma unroll
    for (int r = 0; r < N_RELS; r++) {
        float4 o = make_float4(0.f, 0.f, 0.f, 0.f);
#pragma unroll
        for (int b = 0; b < N_BASES; b++) {
            float cc = c[r * N_BASES + b];
            o.x += cc * bv[b].x; o.y += cc * bv[b].y;
            o.z += cc * bv[b].z; o.w += cc * bv[b].w;
        }
        w4[(size_t)r * NM4 + i] = o;
    }
}

// ---------------- 2: per-(rel,dst) counts ---------------------------------
__global__ void count_kernel(const int* __restrict__ edge_index,
                             const int* __restrict__ edge_type) {
    int e = blockIdx.x * blockDim.x + threadIdx.x;
    if (e >= NEDGE) return;
    int r = edge_type[e];
    int d = edge_index[NEDGE + e];
    atomicAdd(&g_cnt[r * N_ENT + d], 1);
}

// ---------------- 3: scatter msg*norm into agg (one warp per edge) --------
__global__ void scatter_kernel(const int* __restrict__ edge_index,
                               const int* __restrict__ edge_type) {
    int gw = (blockIdx.x * blockDim.x + threadIdx.x) >> 5;
    int lane = threadIdx.x & 31;
    if (gw >= NEDGE) return;
    int r = edge_type[gw];
    int s = edge_index[gw];
    int d = edge_index[NEDGE + gw];
    int c = g_cnt[r * N_ENT + d];
    float norm = 1.0f / (float)(c < 1 ? 1 : c);

    const float4* wrow = (const float4*)(g_weight + ((size_t)r * N_ENT + s) * KGD);
    float4 w = wrow[lane];
    float mx = w.x * norm, my = w.y * norm, mz = w.z * norm, mw = w.w * norm;
    float* dst = g_kg + (size_t)d * KGD + lane * 4;
    asm volatile("red.global.add.v4.f32 [%0], {%1,%2,%3,%4};"
                 :: "l"(dst), "f"(mx), "f"(my), "f"(mz), "f"(mw) : "memory");
}

// ---------------- 4: kg = agg + root + bias --------------------------------
__global__ void finalize_kernel(const float* __restrict__ root,
                                const float* __restrict__ bias) {
    int i = blockIdx.x * blockDim.x + threadIdx.x;  // float4 index
    const int NM4 = (N_ENT * KGD) / 4;
    if (i >= NM4) return;
    float4* kg4 = (float4*)g_kg;
    const float4* r4 = (const float4*)root;
    const float4* b4 = (const float4*)bias;
    float4 a = kg4[i], r = r4[i], b = b4[i & 31];
    a.x += r.x + b.x; a.y += r.y + b.y; a.z += r.z + b.z; a.w += r.w + b.w;
    kg4[i] = a;
}

// ---------------- 5: entity self-dot attention pool ------------------------
// one block per batch, 128 threads
__global__ void ent_attn_kernel(const int* __restrict__ ctx_ent,
                                const float* __restrict__ entW,
                                const float* __restrict__ entb,
                                const float* __restrict__ entv) {
    int b = blockIdx.x;
    int tid = threadIdx.x;   // 0..127
    __shared__ float rep[NCTX][KGD];
    __shared__ float ebuf[NCTX];
    __shared__ float aw[NCTX];
    __shared__ int ids[NCTX];
    __shared__ float wsum[4];

    if (tid < NCTX) ids[tid] = ctx_ent[b * NCTX + tid];
    __syncthreads();
    for (int l = 0; l < NCTX; l++)
        rep[l][tid] = g_kg[(size_t)ids[l] * KGD + tid];
    __syncthreads();

    float wb = entb[tid], wv = entv[tid];
    for (int l = 0; l < NCTX; l++) {
        float acc = 0.f;
#pragma unroll 8
        for (int dd = 0; dd < KGD; dd++)
            acc += rep[l][dd] * entW[dd * KGD + tid];
        float s = tanhf(acc + wb) * wv;
#pragma unroll
        for (int o = 16; o > 0; o >>= 1) s += __shfl_down_sync(0xffffffffu, s, o);
        if ((tid & 31) == 0) wsum[tid >> 5] = s;
        __syncthreads();
        if (tid == 0) ebuf[l] = wsum[0] + wsum[1] + wsum[2] + wsum[3];
        __syncthreads();
    }

    if (tid == 0) {
        float mx = -1e30f;
        for (int l = 0; l < NCTX; l++) {
            float v = (ids[l] != 0) ? ebuf[l] : -1e9f;
            ebuf[l] = v;
            mx = fmaxf(mx, v);
        }
        float sum = 0.f;
        for (int l = 0; l < NCTX; l++) { aw[l] = expf(ebuf[l] - mx); sum += aw[l]; }
        float inv = 1.0f / sum;
        for (int l = 0; l < NCTX; l++) aw[l] *= inv;
    }
    __syncthreads();

    float out = 0.f;
    for (int l = 0; l < NCTX; l++) out += aw[l] * rep[l][tid];
    g_ent_rep[b * KGD + tid] = out;
}

// ---------------- 6: token attention logits GEMM ---------------------------
// e[l] += sum_n v[n] * tanh( (X W)[l,n] + b[n] )
// X: [8192, 768], W: [768, 768].  128x128x16 tile, 8x8 microtile, 256 thr.
__global__ void __launch_bounds__(256, 2)
tok_gemm_kernel(const float* __restrict__ X, const float* __restrict__ W,
                const float* __restrict__ tokb, const float* __restrict__ tokv) {
    const int M = BATCH * SEQL;   // 8192
    const int K = TOKD;           // 768
    __shared__ float Xs[16][132];
    __shared__ float Ws[16][128];
    __shared__ float es[128];

    int tid = threadIdx.x;
    int row0 = blockIdx.x * 128;
    int col0 = blockIdx.y * 128;

    float acc[8][8];
#pragma unroll
    for (int i = 0; i < 8; i++)
#pragma unroll
        for (int j = 0; j < 8; j++) acc[i][j] = 0.f;

    int tm = (tid >> 4) << 3;
    int tn = (tid & 15) << 3;

    for (int k0 = 0; k0 < K; k0 += 16) {
#pragma unroll
        for (int j = 0; j < 2; j++) {
            int lin = tid * 8 + j * 4;
            int r = lin >> 4, c = lin & 15;
            float4 xv = *(const float4*)(X + (size_t)(row0 + r) * K + k0 + c);
            Xs[c + 0][r] = xv.x; Xs[c + 1][r] = xv.y;
            Xs[c + 2][r] = xv.z; Xs[c + 3][r] = xv.w;
            int kr = lin >> 7, cc = lin & 127;
            *(float4*)&Ws[kr][cc] =
                *(const float4*)(W + (size_t)(k0 + kr) * K + col0 + cc);
        }
        __syncthreads();
#pragma unroll
        for (int k = 0; k < 16; k++) {
            float a[8], bb[8];
            *(float4*)&a[0]  = *(const float4*)&Xs[k][tm];
            *(float4*)&a[4]  = *(const float4*)&Xs[k][tm + 4];
            *(float4*)&bb[0] = *(const float4*)&Ws[k][tn];
            *(float4*)&bb[4] = *(const float4*)&Ws[k][tn + 4];
#pragma unroll
            for (int i = 0; i < 8; i++)
#pragma unroll
                for (int j = 0; j < 8; j++) acc[i][j] += a[i] * bb[j];
        }
        __syncthreads();
    }

    if (tid < 128) es[tid] = 0.f;
    __syncthreads();
#pragma unroll
    for (int i = 0; i < 8; i++) {
        float rs = 0.f;
#pragma unroll
        for (int j = 0; j < 8; j++) {
            int n = col0 + tn + j;
            rs += tanhf(acc[i][j] + tokb[n]) * tokv[n];
        }
        atomicAdd(&es[tm + i], rs);
    }
    __syncthreads();
    if (tid < 128) atomicAdd(&g_e_tok[row0 + tid], es[tid]);
}

// ---------------- 7: token softmax+pool, linear, gate, user ----------------
// one block per batch, 256 threads
__global__ void fuse_kernel(const float* __restrict__ X,
                            const int* __restrict__ ctx_tok,
                            const float* __restrict__ linW,
                            const float* __restrict__ linb,
                            const float* __restrict__ gateW,
                            const float* __restrict__ gateb) {
    int b = blockIdx.x;
    int tid = threadIdx.x;   // 0..255
    __shared__ float red[SEQL];
    __shared__ float a[SEQL];
    __shared__ float pool[TOKD];
    __shared__ float tokr[KGD];
    __shared__ float entr[KGD];

    float ev = g_e_tok[b * SEQL + tid];
    bool msk = (ctx_tok[b * SEQL + tid] != 0);
    float val = msk ? ev : -1e9f;

    red[tid] = val;
    __syncthreads();
    for (int s = 128; s > 0; s >>= 1) {
        if (tid < s) red[tid] = fmaxf(red[tid], red[tid + s]);
        __syncthreads();
    }
    float mx = red[0];
    __syncthreads();
    float ex = expf(val - mx);
    red[tid] = ex;
    __syncthreads();
    for (int s = 128; s > 0; s >>= 1) {
        if (tid < s) red[tid] += red[tid + s];
        __syncthreads();
    }
    float inv = 1.0f / red[0];
    a[tid] = ex * inv;
    __syncthreads();

    // pool[d] = sum_l a[l] * X[b,l,d]
    for (int d = tid; d < TOKD; d += 256) {
        float s = 0.f;
        const float* xp = X + (size_t)b * SEQL * TOKD + d;
        for (int l = 0; l < SEQL; l++) s += a[l] * xp[(size_t)l * TOKD];
        pool[d] = s;
    }
    __syncthreads();

    if (tid < KGD) {
        float s = linb[tid];
        const float* wp = linW + (size_t)tid * TOKD;
#pragma unroll 8
        for (int d = 0; d < TOKD; d++) s += pool[d] * wp[d];
        tokr[tid] = s;
        entr[tid] = g_ent_rep[b * KGD + tid];
    }
    __syncthreads();

    if (tid < KGD) {
        float g = gateb[tid];
        const float* gw = gateW + (size_t)tid * (2 * KGD);
#pragma unroll 8
        for (int k = 0; k < KGD; k++) g += gw[k] * tokr[k];
#pragma unroll 8
        for (int k = 0; k < KGD; k++) g += gw[KGD + k] * entr[k];
        g = 1.0f / (1.0f + expf(-g));
        g_user[b * KGD + tid] = g * tokr[tid] + (1.0f - g) * entr[tid];
    }
}

// ---------------- 8: scores = user @ kg^T -----------------------------------
__global__ void scores_kernel(float* __restrict__ out) {
    __shared__ float U[BATCH * KGD];
    int tid = threadIdx.x;
    for (int i = tid; i < BATCH * KGD; i += 256) U[i] = g_user[i];
    __syncthreads();

    int n = blockIdx.x * 256 + tid;
    if (n >= N_ENT) return;

    float acc[BATCH];
#pragma unroll
    for (int b = 0; b < BATCH; b++) acc[b] = 0.f;

    const float4* kgp = (const float4*)(g_kg + (size_t)n * KGD);
#pragma unroll 4
    for (int d4 = 0; d4 < KGD / 4; d4++) {
        float4 kv = kgp[d4];
#pragma unroll
        for (int b = 0; b < BATCH; b++) {
            float4 uv = *(const float4*)&U[b * KGD + d4 * 4];
            acc[b] += kv.x * uv.x + kv.y * uv.y + kv.z * uv.z + kv.w * uv.w;
        }
    }
#pragma unroll
    for (int b = 0; b < BATCH; b++) out[(size_t)b * N_ENT + n] = acc[b];
}

// ---------------- launch ----------------------------------------------------
extern "C" void kernel_launch(void* const* d_in, const int* in_sizes, int n_in,
                              void* d_out, int out_size) {
    const int*   ctx_ent  = (const int*)d_in[0];
    const int*   ctx_tok  = (const int*)d_in[1];
    const int*   edge_idx = (const int*)d_in[2];
    const int*   edge_typ = (const int*)d_in[3];
    const float* tok_emb  = (const float*)d_in[4];
    const float* comp     = (const float*)d_in[5];
    const float* basis    = (const float*)d_in[6];
    const float* root     = (const float*)d_in[7];
    const float* rg_bias  = (const float*)d_in[8];
    const float* entW     = (const float*)d_in[9];
    const float* entb     = (const float*)d_in[10];
    const float* entv     = (const float*)d_in[11];
    const float* tokW     = (const float*)d_in[12];
    const float* tokb     = (const float*)d_in[13];
    const float* tokv     = (const float*)d_in[14];
    const float* linW     = (const float*)d_in[15];
    const float* linb     = (const float*)d_in[16];
    const float* gateW    = (const float*)d_in[17];
    const float* gateb    = (const float*)d_in[18];
    float* out = (float*)d_out;

    zero_kernel<<<2048, 256>>>();
    weight_kernel<<<(960000 + 255) / 256, 256>>>(comp, basis);
    count_kernel<<<(NEDGE + 255) / 256, 256>>>(edge_idx, edge_typ);
    scatter_kernel<<<NEDGE / 8, 256>>>(edge_idx, edge_typ);  // 1 warp/edge
    finalize_kernel<<<(960000 + 255) / 256, 256>>>(root, rg_bias);
    ent_attn_kernel<<<BATCH, 128>>>(ctx_ent, entW, entb, entv);
    tok_gemm_kernel<<<dim3(64, 6), 256>>>(tok_emb, tokW, tokb, tokv);
    fuse_kernel<<<BATCH, 256>>>(tok_emb, ctx_tok, linW, linb, gateW, gateb);
    scores_kernel<<<(N_ENT + 255) / 256, 256>>>(out);
}

// round 3
// speedup vs baseline: 1.3678x; 1.3678x over previous
#include <cuda_runtime.h>
#include <cstdint>

#define N_ENT   30000
#define N_RELS  12
#define N_BASES 8
#define KGD     128
#define TOKD    768
#define BATCH   32
#define NCTX    50
#define SEQL    256
#define NEDGE   400000

// ---------------- scratch (__device__ globals; no allocations allowed) ----
__device__ float g_weight[N_RELS * N_ENT * KGD];   // 184 MB: composed per-rel weights
__device__ float g_kg[N_ENT * KGD];                 // agg -> kg_embedding (in place)
__device__ int   g_cnt[N_RELS * N_ENT];             // per (rel,dst) edge counts
__device__ float g_e_tok[BATCH * SEQL];             // token attention logits
__device__ float g_ent_rep[BATCH * KGD];            // entity_attn_rep
__device__ float g_user[BATCH * KGD];               // user embedding
__device__ float g_Wt[TOKD * TOKD];                 // tok_W transposed: g_Wt[n*K+k] = W[k*K+n]

// ---------------- small PTX helpers ----------------------------------------
__device__ __forceinline__ uint32_t smem_u32(const void* p) {
    uint32_t a;
    asm("{ .reg .u64 t; cvta.to.shared.u64 t, %1; cvt.u32.u64 %0, t; }"
        : "=r"(a) : "l"(p));
    return a;
}

__device__ __forceinline__ void cp16(uint32_t s, const void* g) {
    asm volatile("cp.async.cg.shared.global [%0], [%1], 16;"
                 :: "r"(s), "l"(g) : "memory");
}

__device__ __forceinline__ uint32_t f2tf32(float f) {
    uint32_t r;
    asm("cvt.rna.tf32.f32 %0, %1;" : "=r"(r) : "f"(f));
    return r;
}

__device__ __forceinline__ void mma8(float* c, const uint32_t* a,
                                     uint32_t b0, uint32_t b1) {
    asm volatile(
        "mma.sync.aligned.m16n8k8.row.col.f32.tf32.tf32.f32 "
        "{%0,%1,%2,%3}, {%4,%5,%6,%7}, {%8,%9}, {%0,%1,%2,%3};"
        : "+f"(c[0]), "+f"(c[1]), "+f"(c[2]), "+f"(c[3])
        : "r"(a[0]), "r"(a[1]), "r"(a[2]), "r"(a[3]), "r"(b0), "r"(b1));
}

// ---------------- 0: zero scratch ----------------------------------------
__global__ void zero_kernel() {
    int i = blockIdx.x * blockDim.x + threadIdx.x;
    int stride = gridDim.x * blockDim.x;
    for (int j = i; j < N_ENT * KGD; j += stride) g_kg[j] = 0.f;
    for (int j = i; j < N_RELS * N_ENT; j += stride) g_cnt[j] = 0;
    for (int j = i; j < BATCH * SEQL; j += stride) g_e_tok[j] = 0.f;
}

// ---------------- 1: weight[r,n,d] = sum_b comp[r,b]*basis[b,n,d] --------
__global__ void weight_kernel(const float* __restrict__ comp,
                              const float* __restrict__ basis) {
    __shared__ float c[N_RELS * N_BASES];
    int tid = threadIdx.x;
    if (tid < N_RELS * N_BASES) c[tid] = comp[tid];
    __syncthreads();

    int i = blockIdx.x * blockDim.x + tid;
    const int NM4 = (N_ENT * KGD) / 4;       // 960000
    if (i >= NM4) return;

    float4 bv[N_BASES];
    const float4* b4 = (const float4*)basis;
#pragma unroll
    for (int b = 0; b < N_BASES; b++) bv[b] = b4[(size_t)b * NM4 + i];

    float4* w4 = (float4*)g_weight;
#pragma unroll
    for (int r = 0; r < N_RELS; r++) {
        float4 o = make_float4(0.f, 0.f, 0.f, 0.f);
#pragma unroll
        for (int b = 0; b < N_BASES; b++) {
            float cc = c[r * N_BASES + b];
            o.x += cc * bv[b].x; o.y += cc * bv[b].y;
            o.z += cc * bv[b].z; o.w += cc * bv[b].w;
        }
        w4[(size_t)r * NM4 + i] = o;
    }
}

// ---------------- 2: per-(rel,dst) counts ---------------------------------
__global__ void count_kernel(const int* __restrict__ edge_index,
                             const int* __restrict__ edge_type) {
    int e = blockIdx.x * blockDim.x + threadIdx.x;
    if (e >= NEDGE) return;
    int r = edge_type[e];
    int d = edge_index[NEDGE + e];
    atomicAdd(&g_cnt[r * N_ENT + d], 1);
}

// ---------------- 3: scatter msg*norm into agg (one warp per edge) --------
__global__ void scatter_kernel(const int* __restrict__ edge_index,
                               const int* __restrict__ edge_type) {
    int gw = (blockIdx.x * blockDim.x + threadIdx.x) >> 5;
    int lane = threadIdx.x & 31;
    if (gw >= NEDGE) return;
    int r = edge_type[gw];
    int s = edge_index[gw];
    int d = edge_index[NEDGE + gw];
    int c = g_cnt[r * N_ENT + d];
    float norm = 1.0f / (float)(c < 1 ? 1 : c);

    const float4* wrow = (const float4*)(g_weight + ((size_t)r * N_ENT + s) * KGD);
    float4 w = wrow[lane];
    float mx = w.x * norm, my = w.y * norm, mz = w.z * norm, mw = w.w * norm;
    float* dst = g_kg + (size_t)d * KGD + lane * 4;
    asm volatile("red.global.add.v4.f32 [%0], {%1,%2,%3,%4};"
                 :: "l"(dst), "f"(mx), "f"(my), "f"(mz), "f"(mw) : "memory");
}

// ---------------- 4: kg = agg + root + bias --------------------------------
__global__ void finalize_kernel(const float* __restrict__ root,
                                const float* __restrict__ bias) {
    int i = blockIdx.x * blockDim.x + threadIdx.x;
    const int NM4 = (N_ENT * KGD) / 4;
    if (i >= NM4) return;
    float4* kg4 = (float4*)g_kg;
    const float4* r4 = (const float4*)root;
    const float4* b4 = (const float4*)bias;
    float4 a = kg4[i], r = r4[i], b = b4[i & 31];
    a.x += r.x + b.x; a.y += r.y + b.y; a.z += r.z + b.z; a.w += r.w + b.w;
    kg4[i] = a;
}

// ---------------- 5: entity self-dot attention pool ------------------------
__global__ void ent_attn_kernel(const int* __restrict__ ctx_ent,
                                const float* __restrict__ entW,
                                const float* __restrict__ entb,
                                const float* __restrict__ entv) {
    int b = blockIdx.x;
    int tid = threadIdx.x;   // 0..127
    __shared__ float rep[NCTX][KGD];
    __shared__ float ebuf[NCTX];
    __shared__ float aw[NCTX];
    __shared__ int ids[NCTX];
    __shared__ float wsum[4];

    if (tid < NCTX) ids[tid] = ctx_ent[b * NCTX + tid];
    __syncthreads();
    for (int l = 0; l < NCTX; l++)
        rep[l][tid] = g_kg[(size_t)ids[l] * KGD + tid];
    __syncthreads();

    float wb = entb[tid], wv = entv[tid];
    for (int l = 0; l < NCTX; l++) {
        float acc = 0.f;
#pragma unroll 8
        for (int dd = 0; dd < KGD; dd++)
            acc += rep[l][dd] * entW[dd * KGD + tid];
        float s = tanhf(acc + wb) * wv;
#pragma unroll
        for (int o = 16; o > 0; o >>= 1) s += __shfl_down_sync(0xffffffffu, s, o);
        if ((tid & 31) == 0) wsum[tid >> 5] = s;
        __syncthreads();
        if (tid == 0) ebuf[l] = wsum[0] + wsum[1] + wsum[2] + wsum[3];
        __syncthreads();
    }

    if (tid == 0) {
        float mx = -1e30f;
        for (int l = 0; l < NCTX; l++) {
            float v = (ids[l] != 0) ? ebuf[l] : -1e9f;
            ebuf[l] = v;
            mx = fmaxf(mx, v);
        }
        float sum = 0.f;
        for (int l = 0; l < NCTX; l++) { aw[l] = expf(ebuf[l] - mx); sum += aw[l]; }
        float inv = 1.0f / sum;
        for (int l = 0; l < NCTX; l++) aw[l] *= inv;
    }
    __syncthreads();

    float out = 0.f;
    for (int l = 0; l < NCTX; l++) out += aw[l] * rep[l][tid];
    g_ent_rep[b * KGD + tid] = out;
}

// ---------------- 5b: transpose tok_W into K-major B ------------------------
// g_Wt[n*768 + k] = W[k*768 + n]
__global__ void transpose_kernel(const float* __restrict__ W) {
    __shared__ float t[32][33];
    int bx = blockIdx.x * 32, by = blockIdx.y * 32;
    int tx = threadIdx.x, ty = threadIdx.y;   // 32 x 8
#pragma unroll
    for (int i = 0; i < 32; i += 8)
        t[ty + i][tx] = W[(size_t)(by + ty + i) * TOKD + bx + tx];
    __syncthreads();
#pragma unroll
    for (int i = 0; i < 32; i += 8)
        g_Wt[(size_t)(bx + ty + i) * TOKD + by + tx] = t[tx][ty + i];
}

// ---------------- 6: token attention logits via mma.sync tf32 --------------
// e[m] += sum_n tokv[n] * tanh( (X @ W)[m,n] + tokb[n] )
// CTA tile 128x128, 8 warps (4M x 2N), warp tile 32x64, m16n8k8 tf32.
// K pipelined in chunks of 16 via cp.async double buffer.
#define KCH 16
#define NCHUNK (TOKD / KCH)   // 48
#define LDP 20                // smem row stride in floats (16 + 4 pad)

__device__ __forceinline__ void issue_chunk(const float* __restrict__ X,
                                            int row0, int col0, int c,
                                            float* Asm, float* Bsm, int tid) {
    int k0 = c * KCH;
#pragma unroll
    for (int i = 0; i < 2; i++) {
        int f = tid + i * 256;              // 0..511
        int rr = f >> 2;                    // 0..127
        int c4 = (f & 3) * 4;               // 0,4,8,12
        cp16(smem_u32(Asm + rr * LDP + c4),
             X + (size_t)(row0 + rr) * TOKD + k0 + c4);
        cp16(smem_u32(Bsm + rr * LDP + c4),
             g_Wt + (size_t)(col0 + rr) * TOKD + k0 + c4);
    }
    asm volatile("cp.async.commit_group;" ::: "memory");
}

__global__ void __launch_bounds__(256, 2)
tok_gemm_tc(const float* __restrict__ X,
            const float* __restrict__ tokb,
            const float* __restrict__ tokv) {
    __shared__ float As[2][128 * LDP];
    __shared__ float Bs[2][128 * LDP];

    int tid = threadIdx.x;
    int wid = tid >> 5, lane = tid & 31;
    int gid = lane >> 2, tig = lane & 3;
    int warpM = wid >> 1, warpN = wid & 1;
    int row0 = blockIdx.x * 128, col0 = blockIdx.y * 128;

    float acc[2][8][4];
#pragma unroll
    for (int mi = 0; mi < 2; mi++)
#pragma unroll
        for (int nj = 0; nj < 8; nj++)
#pragma unroll
            for (int q = 0; q < 4; q++) acc[mi][nj][q] = 0.f;

    issue_chunk(X, row0, col0, 0, As[0], Bs[0], tid);

    for (int c = 0; c < NCHUNK; c++) {
        if (c + 1 < NCHUNK) {
            issue_chunk(X, row0, col0, c + 1, As[(c + 1) & 1], Bs[(c + 1) & 1], tid);
            asm volatile("cp.async.wait_group 1;" ::: "memory");
        } else {
            asm volatile("cp.async.wait_group 0;" ::: "memory");
        }
        __syncthreads();

        const float* Ab = As[c & 1];
        const float* Bb = Bs[c & 1];
#pragma unroll
        for (int ks = 0; ks < 2; ks++) {
            int kk = ks * 8 + tig;
            uint32_t a[2][4];
#pragma unroll
            for (int mi = 0; mi < 2; mi++) {
                int rb = warpM * 32 + mi * 16 + gid;
                a[mi][0] = f2tf32(Ab[rb * LDP + kk]);
                a[mi][1] = f2tf32(Ab[(rb + 8) * LDP + kk]);
                a[mi][2] = f2tf32(Ab[rb * LDP + kk + 4]);
                a[mi][3] = f2tf32(Ab[(rb + 8) * LDP + kk + 4]);
            }
#pragma unroll
            for (int nj = 0; nj < 8; nj++) {
                int nb = warpN * 64 + nj * 8 + gid;
                uint32_t b0 = f2tf32(Bb[nb * LDP + kk]);
                uint32_t b1 = f2tf32(Bb[nb * LDP + kk + 4]);
                mma8(acc[0][nj], a[0], b0, b1);
                mma8(acc[1][nj], a[1], b0, b1);
            }
        }
        __syncthreads();
    }

    // epilogue: rs[row] = sum_n tanh(D[row,n] + tokb[n]) * tokv[n]
    float rsum[2][2] = {{0.f, 0.f}, {0.f, 0.f}};
#pragma unroll
    for (int mi = 0; mi < 2; mi++) {
#pragma unroll
        for (int nj = 0; nj < 8; nj++) {
            int n0 = col0 + warpN * 64 + nj * 8 + 2 * tig;
            float bb0 = __ldg(&tokb[n0]), bb1 = __ldg(&tokb[n0 + 1]);
            float vv0 = __ldg(&tokv[n0]), vv1 = __ldg(&tokv[n0 + 1]);
            rsum[mi][0] += tanhf(acc[mi][nj][0] + bb0) * vv0
                         + tanhf(acc[mi][nj][1] + bb1) * vv1;
            rsum[mi][1] += tanhf(acc[mi][nj][2] + bb0) * vv0
                         + tanhf(acc[mi][nj][3] + bb1) * vv1;
        }
    }
#pragma unroll
    for (int mi = 0; mi < 2; mi++)
#pragma unroll
        for (int h = 0; h < 2; h++) {
            float s = rsum[mi][h];
            s += __shfl_xor_sync(0xffffffffu, s, 1);
            s += __shfl_xor_sync(0xffffffffu, s, 2);
            if (tig == 0)
                atomicAdd(&g_e_tok[row0 + warpM * 32 + mi * 16 + h * 8 + gid], s);
        }
}

// ---------------- 7: token softmax+pool, linear, gate, user ----------------
__global__ void fuse_kernel(const float* __restrict__ X,
                            const int* __restrict__ ctx_tok,
                            const float* __restrict__ linW,
                            const float* __restrict__ linb,
                            const float* __restrict__ gateW,
                            const float* __restrict__ gateb) {
    int b = blockIdx.x;
    int tid = threadIdx.x;   // 0..255
    __shared__ float red[SEQL];
    __shared__ float a[SEQL];
    __shared__ float pool[TOKD];
    __shared__ float tokr[KGD];
    __shared__ float entr[KGD];

    float ev = g_e_tok[b * SEQL + tid];
    bool msk = (ctx_tok[b * SEQL + tid] != 0);
    float val = msk ? ev : -1e9f;

    red[tid] = val;
    __syncthreads();
    for (int s = 128; s > 0; s >>= 1) {
        if (tid < s) red[tid] = fmaxf(red[tid], red[tid + s]);
        __syncthreads();
    }
    float mx = red[0];
    __syncthreads();
    float ex = expf(val - mx);
    red[tid] = ex;
    __syncthreads();
    for (int s = 128; s > 0; s >>= 1) {
        if (tid < s) red[tid] += red[tid + s];
        __syncthreads();
    }
    float inv = 1.0f / red[0];
    a[tid] = ex * inv;
    __syncthreads();

    for (int d = tid; d < TOKD; d += 256) {
        float s = 0.f;
        const float* xp = X + (size_t)b * SEQL * TOKD + d;
        for (int l = 0; l < SEQL; l++) s += a[l] * xp[(size_t)l * TOKD];
        pool[d] = s;
    }
    __syncthreads();

    if (tid < KGD) {
        float s = linb[tid];
        const float* wp = linW + (size_t)tid * TOKD;
#pragma unroll 8
        for (int d = 0; d < TOKD; d++) s += pool[d] * wp[d];
        tokr[tid] = s;
        entr[tid] = g_ent_rep[b * KGD + tid];
    }
    __syncthreads();

    if (tid < KGD) {
        float g = gateb[tid];
        const float* gw = gateW + (size_t)tid * (2 * KGD);
#pragma unroll 8
        for (int k = 0; k < KGD; k++) g += gw[k] * tokr[k];
#pragma unroll 8
        for (int k = 0; k < KGD; k++) g += gw[KGD + k] * entr[k];
        g = 1.0f / (1.0f + expf(-g));
        g_user[b * KGD + tid] = g * tokr[tid] + (1.0f - g) * entr[tid];
    }
}

// ---------------- 8: scores = user @ kg^T -----------------------------------
__global__ void scores_kernel(float* __restrict__ out) {
    __shared__ float U[BATCH * KGD];
    int tid = threadIdx.x;
    for (int i = tid; i < BATCH * KGD; i += 256) U[i] = g_user[i];
    __syncthreads();

    int n = blockIdx.x * 256 + tid;
    if (n >= N_ENT) return;

    float acc[BATCH];
#pragma unroll
    for (int b = 0; b < BATCH; b++) acc[b] = 0.f;

    const float4* kgp = (const float4*)(g_kg + (size_t)n * KGD);
#pragma unroll 4
    for (int d4 = 0; d4 < KGD / 4; d4++) {
        float4 kv = kgp[d4];
#pragma unroll
        for (int b = 0; b < BATCH; b++) {
            float4 uv = *(const float4*)&U[b * KGD + d4 * 4];
            acc[b] += kv.x * uv.x + kv.y * uv.y + kv.z * uv.z + kv.w * uv.w;
        }
    }
#pragma unroll
    for (int b = 0; b < BATCH; b++) out[(size_t)b * N_ENT + n] = acc[b];
}

// ---------------- launch ----------------------------------------------------
extern "C" void kernel_launch(void* const* d_in, const int* in_sizes, int n_in,
                              void* d_out, int out_size) {
    const int*   ctx_ent  = (const int*)d_in[0];
    const int*   ctx_tok  = (const int*)d_in[1];
    const int*   edge_idx = (const int*)d_in[2];
    const int*   edge_typ = (const int*)d_in[3];
    const float* tok_emb  = (const float*)d_in[4];
    const float* comp     = (const float*)d_in[5];
    const float* basis    = (const float*)d_in[6];
    const float* root     = (const float*)d_in[7];
    const float* rg_bias  = (const float*)d_in[8];
    const float* entW     = (const float*)d_in[9];
    const float* entb     = (const float*)d_in[10];
    const float* entv     = (const float*)d_in[11];
    const float* tokW     = (const float*)d_in[12];
    const float* tokb     = (const float*)d_in[13];
    const float* tokv     = (const float*)d_in[14];
    const float* linW     = (const float*)d_in[15];
    const float* linb     = (const float*)d_in[16];
    const float* gateW    = (const float*)d_in[17];
    const float* gateb    = (const float*)d_in[18];
    float* out = (float*)d_out;

    zero_kernel<<<2048, 256>>>();
    weight_kernel<<<(960000 + 255) / 256, 256>>>(comp, basis);
    count_kernel<<<(NEDGE + 255) / 256, 256>>>(edge_idx, edge_typ);
    scatter_kernel<<<NEDGE / 8, 256>>>(edge_idx, edge_typ);  // 1 warp/edge
    finalize_kernel<<<(960000 + 255) / 256, 256>>>(root, rg_bias);
    ent_attn_kernel<<<BATCH, 128>>>(ctx_ent, entW, entb, entv);
    transpose_kernel<<<dim3(TOKD / 32, TOKD / 32), dim3(32, 8)>>>(tokW);
    tok_gemm_tc<<<dim3(64, 6), 256>>>(tok_emb, tokb, tokv);
    fuse_kernel<<<BATCH, 256>>>(tok_emb, ctx_tok, linW, linb, gateW, gateb);
    scores_kernel<<<(N_ENT + 255) / 256, 256>>>(out);
}

// round 4
// speedup vs baseline: 1.4146x; 1.0342x over previous
#include <cuda_runtime.h>
#include <cuda_bf16.h>
#include <cstdint>

#define N_ENT   30000
#define N_RELS  12
#define N_BASES 8
#define KGD     128
#define TOKD    768
#define BATCH   32
#define NCTX    50
#define SEQL    256
#define NEDGE   400000

// ---------------- scratch (__device__ globals; no allocations allowed) ----
__device__ __align__(256) __nv_bfloat16 g_wbf[N_RELS * N_ENT * KGD]; // 92 MB bf16 weights
__device__ float g_kg[N_ENT * KGD];                 // agg -> kg_embedding (in place)
__device__ int   g_cnt[N_RELS * N_ENT];             // per (rel,dst) edge counts
__device__ float g_e_tok[BATCH * SEQL];             // token attention logits
__device__ float g_ent_rep[BATCH * KGD];            // entity_attn_rep
__device__ float g_user[BATCH * KGD];               // user embedding
__device__ float g_Wt[TOKD * TOKD];                 // tok_W^T, pre-rounded to tf32

// ---------------- small PTX helpers ----------------------------------------
__device__ __forceinline__ uint32_t smem_u32(const void* p) {
    uint32_t a;
    asm("{ .reg .u64 t; cvta.to.shared.u64 t, %1; cvt.u32.u64 %0, t; }"
        : "=r"(a) : "l"(p));
    return a;
}

__device__ __forceinline__ void cp16(uint32_t s, const void* g) {
    asm volatile("cp.async.cg.shared.global [%0], [%1], 16;"
                 :: "r"(s), "l"(g) : "memory");
}

__device__ __forceinline__ uint32_t f2tf32(float f) {
    uint32_t r;
    asm("cvt.rna.tf32.f32 %0, %1;" : "=r"(r) : "f"(f));
    return r;
}

__device__ __forceinline__ void mma8(float* c, const uint32_t* a,
                                     uint32_t b0, uint32_t b1) {
    asm volatile(
        "mma.sync.aligned.m16n8k8.row.col.f32.tf32.tf32.f32 "
        "{%0,%1,%2,%3}, {%4,%5,%6,%7}, {%8,%9}, {%0,%1,%2,%3};"
        : "+f"(c[0]), "+f"(c[1]), "+f"(c[2]), "+f"(c[3])
        : "r"(a[0]), "r"(a[1]), "r"(a[2]), "r"(a[3]), "r"(b0), "r"(b1));
}

__device__ __forceinline__ uint32_t pack_bf16(float a, float b) {
    __nv_bfloat162 h = __floats2bfloat162_rn(a, b);
    return *(uint32_t*)&h;
}

// ---------------- 0: zero scratch ----------------------------------------
__global__ void zero_kernel() {
    int i = blockIdx.x * blockDim.x + threadIdx.x;
    int stride = gridDim.x * blockDim.x;
    for (int j = i; j < N_ENT * KGD; j += stride) g_kg[j] = 0.f;
    for (int j = i; j < N_RELS * N_ENT; j += stride) g_cnt[j] = 0;
    for (int j = i; j < BATCH * SEQL; j += stride) g_e_tok[j] = 0.f;
}

// ---------------- 1: wbf[r,n,d] = bf16( sum_b comp[r,b]*basis[b,n,d] ) ----
__global__ void weight_kernel(const float* __restrict__ comp,
                              const float* __restrict__ basis) {
    __shared__ float c[N_RELS * N_BASES];
    int tid = threadIdx.x;
    if (tid < N_RELS * N_BASES) c[tid] = comp[tid];
    __syncthreads();

    int i = blockIdx.x * blockDim.x + tid;
    const int NM4 = (N_ENT * KGD) / 4;       // 960000
    if (i >= NM4) return;

    float4 bv[N_BASES];
    const float4* b4 = (const float4*)basis;
#pragma unroll
    for (int b = 0; b < N_BASES; b++) bv[b] = b4[(size_t)b * NM4 + i];

#pragma unroll
    for (int r = 0; r < N_RELS; r++) {
        float4 o = make_float4(0.f, 0.f, 0.f, 0.f);
#pragma unroll
        for (int b = 0; b < N_BASES; b++) {
            float cc = c[r * N_BASES + b];
            o.x += cc * bv[b].x; o.y += cc * bv[b].y;
            o.z += cc * bv[b].z; o.w += cc * bv[b].w;
        }
        uint2 p = make_uint2(pack_bf16(o.x, o.y), pack_bf16(o.z, o.w));
        __stcs((uint2*)(g_wbf + ((size_t)r * NM4 + i) * 4), p);
    }
}

// ---------------- 2: per-(rel,dst) counts ---------------------------------
__global__ void count_kernel(const int* __restrict__ edge_index,
                             const int* __restrict__ edge_type) {
    int e = blockIdx.x * blockDim.x + threadIdx.x;
    if (e >= NEDGE) return;
    int r = edge_type[e];
    int d = edge_index[NEDGE + e];
    atomicAdd(&g_cnt[r * N_ENT + d], 1);
}

// ---------------- 3: scatter msg*norm into agg (2 edges per warp) ---------
// 16 lanes per edge; each lane loads 8 bf16 (16B) and issues 2x red.v4.
__global__ void scatter_kernel(const int* __restrict__ edge_index,
                               const int* __restrict__ edge_type) {
    int gw = (blockIdx.x * blockDim.x + threadIdx.x) >> 5;
    int lane = threadIdx.x & 31;
    int e = gw * 2 + (lane >> 4);
    int sub = lane & 15;
    if (e >= NEDGE) return;
    int r = edge_type[e];
    int s = edge_index[e];
    int d = edge_index[NEDGE + e];
    int c = g_cnt[r * N_ENT + d];
    float norm = 1.0f / (float)(c < 1 ? 1 : c);

    const uint4* row = (const uint4*)(g_wbf + ((size_t)r * N_ENT + s) * KGD);
    uint4 w = __ldcs(row + sub);

    float f[8];
    f[0] = __uint_as_float(w.x << 16)        * norm;
    f[1] = __uint_as_float(w.x & 0xffff0000u) * norm;
    f[2] = __uint_as_float(w.y << 16)        * norm;
    f[3] = __uint_as_float(w.y & 0xffff0000u) * norm;
    f[4] = __uint_as_float(w.z << 16)        * norm;
    f[5] = __uint_as_float(w.z & 0xffff0000u) * norm;
    f[6] = __uint_as_float(w.w << 16)        * norm;
    f[7] = __uint_as_float(w.w & 0xffff0000u) * norm;

    float* dst = g_kg + (size_t)d * KGD + sub * 8;
    asm volatile("red.global.add.v4.f32 [%0], {%1,%2,%3,%4};"
                 :: "l"(dst), "f"(f[0]), "f"(f[1]), "f"(f[2]), "f"(f[3]) : "memory");
    asm volatile("red.global.add.v4.f32 [%0], {%1,%2,%3,%4};"
                 :: "l"(dst + 4), "f"(f[4]), "f"(f[5]), "f"(f[6]), "f"(f[7]) : "memory");
}

// ---------------- 4: kg = agg + root + bias --------------------------------
__global__ void finalize_kernel(const float* __restrict__ root,
                                const float* __restrict__ bias) {
    int i = blockIdx.x * blockDim.x + threadIdx.x;
    const int NM4 = (N_ENT * KGD) / 4;
    if (i >= NM4) return;
    float4* kg4 = (float4*)g_kg;
    const float4* r4 = (const float4*)root;
    const float4* b4 = (const float4*)bias;
    float4 a = kg4[i], r = r4[i], b = b4[i & 31];
    a.x += r.x + b.x; a.y += r.y + b.y; a.z += r.z + b.z; a.w += r.w + b.w;
    kg4[i] = a;
}

// ---------------- 5: entity self-dot attention pool ------------------------
__global__ void ent_attn_kernel(const int* __restrict__ ctx_ent,
                                const float* __restrict__ entW,
                                const float* __restrict__ entb,
                                const float* __restrict__ entv) {
    int b = blockIdx.x;
    int tid = threadIdx.x;   // 0..127
    __shared__ float rep[NCTX][KGD];
    __shared__ float ebuf[NCTX];
    __shared__ float aw[NCTX];
    __shared__ int ids[NCTX];
    __shared__ float wsum[4];

    if (tid < NCTX) ids[tid] = ctx_ent[b * NCTX + tid];
    __syncthreads();
    for (int l = 0; l < NCTX; l++)
        rep[l][tid] = g_kg[(size_t)ids[l] * KGD + tid];
    __syncthreads();

    float wb = entb[tid], wv = entv[tid];
    for (int l = 0; l < NCTX; l++) {
        float acc = 0.f;
#pragma unroll 8
        for (int dd = 0; dd < KGD; dd++)
            acc += rep[l][dd] * entW[dd * KGD + tid];
        float s = tanhf(acc + wb) * wv;
#pragma unroll
        for (int o = 16; o > 0; o >>= 1) s += __shfl_down_sync(0xffffffffu, s, o);
        if ((tid & 31) == 0) wsum[tid >> 5] = s;
        __syncthreads();
        if (tid == 0) ebuf[l] = wsum[0] + wsum[1] + wsum[2] + wsum[3];
        __syncthreads();
    }

    if (tid == 0) {
        float mx = -1e30f;
        for (int l = 0; l < NCTX; l++) {
            float v = (ids[l] != 0) ? ebuf[l] : -1e9f;
            ebuf[l] = v;
            mx = fmaxf(mx, v);
        }
        float sum = 0.f;
        for (int l = 0; l < NCTX; l++) { aw[l] = expf(ebuf[l] - mx); sum += aw[l]; }
        float inv = 1.0f / sum;
        for (int l = 0; l < NCTX; l++) aw[l] *= inv;
    }
    __syncthreads();

    float out = 0.f;
    for (int l = 0; l < NCTX; l++) out += aw[l] * rep[l][tid];
    g_ent_rep[b * KGD + tid] = out;
}

// ---------------- 5b: transpose tok_W, pre-rounded to tf32 -----------------
// g_Wt[n*768 + k] = tf32_rna( W[k*768 + n] )
__global__ void transpose_kernel(const float* __restrict__ W) {
    __shared__ float t[32][33];
    int bx = blockIdx.x * 32, by = blockIdx.y * 32;
    int tx = threadIdx.x, ty = threadIdx.y;   // 32 x 8
#pragma unroll
    for (int i = 0; i < 32; i += 8)
        t[ty + i][tx] = W[(size_t)(by + ty + i) * TOKD + bx + tx];
    __syncthreads();
#pragma unroll
    for (int i = 0; i < 32; i += 8)
        g_Wt[(size_t)(bx + ty + i) * TOKD + by + tx] =
            __uint_as_float(f2tf32(t[tx][ty + i]));
}

// ---------------- 6: token attention logits via mma.sync tf32 --------------
#define KCH 16
#define NCHUNK (TOKD / KCH)   // 48
#define LDP 20                // smem row stride in floats (16 + 4 pad)

__device__ __forceinline__ void issue_chunk(const float* __restrict__ X,
                                            int row0, int col0, int c,
                                            float* Asm, float* Bsm, int tid) {
    int k0 = c * KCH;
#pragma unroll
    for (int i = 0; i < 2; i++) {
        int f = tid + i * 256;              // 0..511
        int rr = f >> 2;                    // 0..127
        int c4 = (f & 3) * 4;               // 0,4,8,12
        cp16(smem_u32(Asm + rr * LDP + c4),
             X + (size_t)(row0 + rr) * TOKD + k0 + c4);
        cp16(smem_u32(Bsm + rr * LDP + c4),
             g_Wt + (size_t)(col0 + rr) * TOKD + k0 + c4);
    }
    asm volatile("cp.async.commit_group;" ::: "memory");
}

__global__ void __launch_bounds__(256, 2)
tok_gemm_tc(const float* __restrict__ X,
            const float* __restrict__ tokb,
            const float* __restrict__ tokv) {
    __shared__ float As[2][128 * LDP];
    __shared__ float Bs[2][128 * LDP];

    int tid = threadIdx.x;
    int wid = tid >> 5, lane = tid & 31;
    int gid = lane >> 2, tig = lane & 3;
    int warpM = wid >> 1, warpN = wid & 1;
    int row0 = blockIdx.x * 128, col0 = blockIdx.y * 128;

    float acc[2][8][4];
#pragma unroll
    for (int mi = 0; mi < 2; mi++)
#pragma unroll
        for (int nj = 0; nj < 8; nj++)
#pragma unroll
            for (int q = 0; q < 4; q++) acc[mi][nj][q] = 0.f;

    issue_chunk(X, row0, col0, 0, As[0], Bs[0], tid);

    for (int c = 0; c < NCHUNK; c++) {
        if (c + 1 < NCHUNK) {
            issue_chunk(X, row0, col0, c + 1, As[(c + 1) & 1], Bs[(c + 1) & 1], tid);
            asm volatile("cp.async.wait_group 1;" ::: "memory");
        } else {
            asm volatile("cp.async.wait_group 0;" ::: "memory");
        }
        __syncthreads();

        const float* Ab = As[c & 1];
        const float* Bb = Bs[c & 1];
#pragma unroll
        for (int ks = 0; ks < 2; ks++) {
            int kk = ks * 8 + tig;
            uint32_t a[2][4];
#pragma unroll
            for (int mi = 0; mi < 2; mi++) {
                int rb = warpM * 32 + mi * 16 + gid;
                a[mi][0] = __float_as_uint(Ab[rb * LDP + kk]);
                a[mi][1] = __float_as_uint(Ab[(rb + 8) * LDP + kk]);
                a[mi][2] = __float_as_uint(Ab[rb * LDP + kk + 4]);
                a[mi][3] = __float_as_uint(Ab[(rb + 8) * LDP + kk + 4]);
            }
#pragma unroll
            for (int nj = 0; nj < 8; nj++) {
                int nb = warpN * 64 + nj * 8 + gid;
                uint32_t b0 = __float_as_uint(Bb[nb * LDP + kk]);
                uint32_t b1 = __float_as_uint(Bb[nb * LDP + kk + 4]);
                mma8(acc[0][nj], a[0], b0, b1);
                mma8(acc[1][nj], a[1], b0, b1);
            }
        }
        __syncthreads();
    }

    // epilogue: rs[row] = sum_n tanh(D[row,n] + tokb[n]) * tokv[n]
    float rsum[2][2] = {{0.f, 0.f}, {0.f, 0.f}};
#pragma unroll
    for (int mi = 0; mi < 2; mi++) {
#pragma unroll
        for (int nj = 0; nj < 8; nj++) {
            int n0 = col0 + warpN * 64 + nj * 8 + 2 * tig;
            float bb0 = __ldg(&tokb[n0]), bb1 = __ldg(&tokb[n0 + 1]);
            float vv0 = __ldg(&tokv[n0]), vv1 = __ldg(&tokv[n0 + 1]);
            rsum[mi][0] += tanhf(acc[mi][nj][0] + bb0) * vv0
                         + tanhf(acc[mi][nj][1] + bb1) * vv1;
            rsum[mi][1] += tanhf(acc[mi][nj][2] + bb0) * vv0
                         + tanhf(acc[mi][nj][3] + bb1) * vv1;
        }
    }
#pragma unroll
    for (int mi = 0; mi < 2; mi++)
#pragma unroll
        for (int h = 0; h < 2; h++) {
            float s = rsum[mi][h];
            s += __shfl_xor_sync(0xffffffffu, s, 1);
            s += __shfl_xor_sync(0xffffffffu, s, 2);
            if (tig == 0)
                atomicAdd(&g_e_tok[row0 + warpM * 32 + mi * 16 + h * 8 + gid], s);
        }
}

// ---------------- 7: token softmax+pool, linear, gate, user ----------------
__global__ void fuse_kernel(const float* __restrict__ X,
                            const int* __restrict__ ctx_tok,
                            const float* __restrict__ linW,
                            const float* __restrict__ linb,
                            const float* __restrict__ gateW,
                            const float* __restrict__ gateb) {
    int b = blockIdx.x;
    int tid = threadIdx.x;   // 0..255
    __shared__ float red[SEQL];
    __shared__ float a[SEQL];
    __shared__ float pool[TOKD];
    __shared__ float tokr[KGD];
    __shared__ float entr[KGD];

    float ev = g_e_tok[b * SEQL + tid];
    bool msk = (ctx_tok[b * SEQL + tid] != 0);
    float val = msk ? ev : -1e9f;

    red[tid] = val;
    __syncthreads();
    for (int s = 128; s > 0; s >>= 1) {
        if (tid < s) red[tid] = fmaxf(red[tid], red[tid + s]);
        __syncthreads();
    }
    float mx = red[0];
    __syncthreads();
    float ex = expf(val - mx);
    red[tid] = ex;
    __syncthreads();
    for (int s = 128; s > 0; s >>= 1) {
        if (tid < s) red[tid] += red[tid + s];
        __syncthreads();
    }
    float inv = 1.0f / red[0];
    a[tid] = ex * inv;
    __syncthreads();

    for (int d = tid; d < TOKD; d += 256) {
        float s0 = 0.f, s1 = 0.f;
        const float* xp = X + (size_t)b * SEQL * TOKD + d;
#pragma unroll 8
        for (int l = 0; l < SEQL; l += 2) {
            s0 += a[l] * xp[(size_t)l * TOKD];
            s1 += a[l + 1] * xp[(size_t)(l + 1) * TOKD];
        }
        pool[d] = s0 + s1;
    }
    __syncthreads();

    if (tid < KGD) {
        float s = linb[tid];
        const float* wp = linW + (size_t)tid * TOKD;
#pragma unroll 8
        for (int d = 0; d < TOKD; d++) s += pool[d] * wp[d];
        tokr[tid] = s;
        entr[tid] = g_ent_rep[b * KGD + tid];
    }
    __syncthreads();

    if (tid < KGD) {
        float g = gateb[tid];
        const float* gw = gateW + (size_t)tid * (2 * KGD);
#pragma unroll 8
        for (int k = 0; k < KGD; k++) g += gw[k] * tokr[k];
#pragma unroll 8
        for (int k = 0; k < KGD; k++) g += gw[KGD + k] * entr[k];
        g = 1.0f / (1.0f + expf(-g));
        g_user[b * KGD + tid] = g * tokr[tid] + (1.0f - g) * entr[tid];
    }
}

// ---------------- 8: scores = user @ kg^T -----------------------------------
__global__ void scores_kernel(float* __restrict__ out) {
    __shared__ float U[BATCH * KGD];
    int tid = threadIdx.x;
    for (int i = tid; i < BATCH * KGD; i += 256) U[i] = g_user[i];
    __syncthreads();

    int n = blockIdx.x * 256 + tid;
    if (n >= N_ENT) return;

    float acc[BATCH];
#pragma unroll
    for (int b = 0; b < BATCH; b++) acc[b] = 0.f;

    const float4* kgp = (const float4*)(g_kg + (size_t)n * KGD);
#pragma unroll 4
    for (int d4 = 0; d4 < KGD / 4; d4++) {
        float4 kv = kgp[d4];
#pragma unroll
        for (int b = 0; b < BATCH; b++) {
            float4 uv = *(const float4*)&U[b * KGD + d4 * 4];
            acc[b] += kv.x * uv.x + kv.y * uv.y + kv.z * uv.z + kv.w * uv.w;
        }
    }
#pragma unroll
    for (int b = 0; b < BATCH; b++) out[(size_t)b * N_ENT + n] = acc[b];
}

// ---------------- launch ----------------------------------------------------
extern "C" void kernel_launch(void* const* d_in, const int* in_sizes, int n_in,
                              void* d_out, int out_size) {
    const int*   ctx_ent  = (const int*)d_in[0];
    const int*   ctx_tok  = (const int*)d_in[1];
    const int*   edge_idx = (const int*)d_in[2];
    const int*   edge_typ = (const int*)d_in[3];
    const float* tok_emb  = (const float*)d_in[4];
    const float* comp     = (const float*)d_in[5];
    const float* basis    = (const float*)d_in[6];
    const float* root     = (const float*)d_in[7];
    const float* rg_bias  = (const float*)d_in[8];
    const float* entW     = (const float*)d_in[9];
    const float* entb     = (const float*)d_in[10];
    const float* entv     = (const float*)d_in[11];
    const float* tokW     = (const float*)d_in[12];
    const float* tokb     = (const float*)d_in[13];
    const float* tokv     = (const float*)d_in[14];
    const float* linW     = (const float*)d_in[15];
    const float* linb     = (const float*)d_in[16];
    const float* gateW    = (const float*)d_in[17];
    const float* gateb    = (const float*)d_in[18];
    float* out = (float*)d_out;

    zero_kernel<<<2048, 256>>>();
    weight_kernel<<<(960000 + 255) / 256, 256>>>(comp, basis);
    count_kernel<<<(NEDGE + 255) / 256, 256>>>(edge_idx, edge_typ);
    scatter_kernel<<<25000, 256>>>(edge_idx, edge_typ);  // 2 edges/warp
    finalize_kernel<<<(960000 + 255) / 256, 256>>>(root, rg_bias);
    ent_attn_kernel<<<BATCH, 128>>>(ctx_ent, entW, entb, entv);
    transpose_kernel<<<dim3(TOKD / 32, TOKD / 32), dim3(32, 8)>>>(tokW);
    tok_gemm_tc<<<dim3(64, 6), 256>>>(tok_emb, tokb, tokv);
    fuse_kernel<<<BATCH, 256>>>(tok_emb, ctx_tok, linW, linb, gateW, gateb);
    scores_kernel<<<(N_ENT + 255) / 256, 256>>>(out);
}

// round 6
// speedup vs baseline: 1.4317x; 1.0121x over previous
#include <cuda_runtime.h>
#include <cuda_bf16.h>
#include <cstdint>

#define N_ENT   30000
#define N_RELS  12
#define N_BASES 8
#define KGD     128
#define TOKD    768
#define BATCH   32
#define NCTX    50
#define SEQL    256
#define NEDGE   400000

// ---------------- scratch (__device__ globals; no allocations allowed) ----
__device__ __align__(256) __nv_bfloat16 g_wbf[N_RELS * N_ENT * KGD]; // 92 MB bf16 weights
__device__ float g_kg[N_ENT * KGD];                 // kg_embedding
__device__ int   g_cnt[N_RELS * N_ENT];             // per (rel,dst) edge counts
__device__ int   g_deg[N_ENT];                      // per-dst degree
__device__ int   g_off[N_ENT + 1];                  // exclusive scan of degree
__device__ int   g_pos[N_ENT];                      // running placement counters
__device__ uint32_t g_sorted[NEDGE];                // dst-bucketed (r<<16|src)
__device__ float g_e_tok[BATCH * SEQL];             // token attention logits
__device__ float g_a[BATCH * SEQL];                 // token attention weights
__device__ float g_pool[BATCH * TOKD];              // pooled token rep
__device__ float g_ent_rep[BATCH * KGD];            // entity_attn_rep
__device__ float g_user[BATCH * KGD];               // user embedding
__device__ float g_Wt[TOKD * TOKD];                 // tok_W^T, pre-rounded to tf32

// ---------------- small PTX helpers ----------------------------------------
__device__ __forceinline__ uint32_t smem_u32(const void* p) {
    uint32_t a;
    asm("{ .reg .u64 t; cvta.to.shared.u64 t, %1; cvt.u32.u64 %0, t; }"
        : "=r"(a) : "l"(p));
    return a;
}

__device__ __forceinline__ void cp16(uint32_t s, const void* g) {
    asm volatile("cp.async.cg.shared.global [%0], [%1], 16;"
                 :: "r"(s), "l"(g) : "memory");
}

__device__ __forceinline__ uint32_t f2tf32(float f) {
    uint32_t r;
    asm("cvt.rna.tf32.f32 %0, %1;" : "=r"(r) : "f"(f));
    return r;
}

__device__ __forceinline__ void mma8(float* c, const uint32_t* a,
                                     uint32_t b0, uint32_t b1) {
    asm volatile(
        "mma.sync.aligned.m16n8k8.row.col.f32.tf32.tf32.f32 "
        "{%0,%1,%2,%3}, {%4,%5,%6,%7}, {%8,%9}, {%0,%1,%2,%3};"
        : "+f"(c[0]), "+f"(c[1]), "+f"(c[2]), "+f"(c[3])
        : "r"(a[0]), "r"(a[1]), "r"(a[2]), "r"(a[3]), "r"(b0), "r"(b1));
}

__device__ __forceinline__ uint32_t pack_bf16(float a, float b) {
    __nv_bfloat162 h = __floats2bfloat162_rn(a, b);
    return *(uint32_t*)&h;
}

// ---------------- 0: zero scratch ----------------------------------------
__global__ void zero_kernel() {
    int i = blockIdx.x * blockDim.x + threadIdx.x;
    int stride = gridDim.x * blockDim.x;
    for (int j = i; j < N_RELS * N_ENT; j += stride) g_cnt[j] = 0;
    for (int j = i; j < N_ENT; j += stride) { g_deg[j] = 0; g_pos[j] = 0; }
    for (int j = i; j < BATCH * SEQL; j += stride) g_e_tok[j] = 0.f;
}

// ---------------- 1: wbf[r,n,d] = bf16( sum_b comp[r,b]*basis[b,n,d] ) ----
// plain stores: keep the 92 MB table L2-resident for the aggregate gather.
__global__ void weight_kernel(const float* __restrict__ comp,
                              const float* __restrict__ basis) {
    __shared__ float c[N_RELS * N_BASES];
    int tid = threadIdx.x;
    if (tid < N_RELS * N_BASES) c[tid] = comp[tid];
    __syncthreads();

    int i = blockIdx.x * blockDim.x + tid;
    const int NM4 = (N_ENT * KGD) / 4;       // 960000
    if (i >= NM4) return;

    float4 bv[N_BASES];
    const float4* b4 = (const float4*)basis;
#pragma unroll
    for (int b = 0; b < N_BASES; b++) bv[b] = b4[(size_t)b * NM4 + i];

#pragma unroll
    for (int r = 0; r < N_RELS; r++) {
        float4 o = make_float4(0.f, 0.f, 0.f, 0.f);
#pragma unroll
        for (int b = 0; b < N_BASES; b++) {
            float cc = c[r * N_BASES + b];
            o.x += cc * bv[b].x; o.y += cc * bv[b].y;
            o.z += cc * bv[b].z; o.w += cc * bv[b].w;
        }
        uint2 p = make_uint2(pack_bf16(o.x, o.y), pack_bf16(o.z, o.w));
        *((uint2*)(g_wbf + ((size_t)r * NM4 + i) * 4)) = p;
    }
}

// ---------------- 2: per-(rel,dst) counts + per-dst degree ----------------
__global__ void count_kernel(const int* __restrict__ edge_index,
                             const int* __restrict__ edge_type) {
    int e = blockIdx.x * blockDim.x + threadIdx.x;
    if (e >= NEDGE) return;
    int r = edge_type[e];
    int d = edge_index[NEDGE + e];
    atomicAdd(&g_cnt[r * N_ENT + d], 1);
    atomicAdd(&g_deg[d], 1);
}

// ---------------- 3a: exclusive scan of degree (single CTA) ----------------
#define SCAN_PER 30   // 1024 * 30 = 30720 >= 30000
__global__ void scan_kernel() {
    __shared__ int part[1024];
    int t = threadIdx.x;
    int base = t * SCAN_PER;
    int s = 0;
#pragma unroll
    for (int j = 0; j < SCAN_PER; j++) {
        int idx = base + j;
        if (idx < N_ENT) s += g_deg[idx];
    }
    part[t] = s;
    __syncthreads();
    // Hillis-Steele inclusive scan
    for (int off = 1; off < 1024; off <<= 1) {
        int v = (t >= off) ? part[t - off] : 0;
        __syncthreads();
        part[t] += v;
        __syncthreads();
    }
    int run = part[t] - s;   // exclusive prefix
#pragma unroll
    for (int j = 0; j < SCAN_PER; j++) {
        int idx = base + j;
        if (idx < N_ENT) { g_off[idx] = run; run += g_deg[idx]; }
    }
    if (t == 1023) g_off[N_ENT] = part[1023];
}

// ---------------- 3b: place edges into dst buckets --------------------------
__global__ void place_kernel(const int* __restrict__ edge_index,
                             const int* __restrict__ edge_type) {
    int e = blockIdx.x * blockDim.x + threadIdx.x;
    if (e >= NEDGE) return;
    int r = edge_type[e];
    int s = edge_index[e];
    int d = edge_index[NEDGE + e];
    int p = atomicAdd(&g_pos[d], 1);
    g_sorted[g_off[d] + p] = ((uint32_t)r << 16) | (uint32_t)s;
}

// ---------------- 3c: aggregate (1 warp per dst) + root + bias -------------
__global__ void aggregate_kernel(const float* __restrict__ root,
                                 const float* __restrict__ bias) {
    int w = (blockIdx.x * blockDim.x + threadIdx.x) >> 5;
    int lane = threadIdx.x & 31;
    if (w >= N_ENT) return;
    int d = w;
    int beg = g_off[d], end = g_off[d + 1];

    float a0 = 0.f, a1 = 0.f, a2 = 0.f, a3 = 0.f;
    for (int i = beg; i < end; i++) {
        uint32_t rec = __ldg(&g_sorted[i]);       // warp-uniform
        int r = rec >> 16, s = rec & 0xffff;
        int c = __ldg(&g_cnt[r * N_ENT + d]);     // warp-uniform, L2-hot
        float norm = 1.0f / (float)(c < 1 ? 1 : c);
        uint2 ww = *(const uint2*)(g_wbf + ((size_t)r * N_ENT + s) * KGD + lane * 4);
        a0 += __uint_as_float(ww.x << 16)          * norm;
        a1 += __uint_as_float(ww.x & 0xffff0000u)  * norm;
        a2 += __uint_as_float(ww.y << 16)          * norm;
        a3 += __uint_as_float(ww.y & 0xffff0000u)  * norm;
    }
    int o = d * KGD + lane * 4;
    float4 r4 = *(const float4*)(root + o);
    float4 b4 = *(const float4*)(bias + lane * 4);
    float4 outv = make_float4(a0 + r4.x + b4.x, a1 + r4.y + b4.y,
                              a2 + r4.z + b4.z, a3 + r4.w + b4.w);
    *(float4*)(g_kg + o) = outv;
}

// ---------------- 5: entity self-dot attention pool ------------------------
// (round-4 proven version: entW read from gmem, coalesced across tid)
__global__ void ent_attn_kernel(const int* __restrict__ ctx_ent,
                                const float* __restrict__ entW,
                                const float* __restrict__ entb,
                                const float* __restrict__ entv) {
    int b = blockIdx.x;
    int tid = threadIdx.x;   // 0..127
    __shared__ float rep[NCTX][KGD];
    __shared__ float ebuf[NCTX];
    __shared__ float aw[NCTX];
    __shared__ int ids[NCTX];
    __shared__ float wsum[4];

    if (tid < NCTX) ids[tid] = ctx_ent[b * NCTX + tid];
    __syncthreads();
    for (int l = 0; l < NCTX; l++)
        rep[l][tid] = g_kg[(size_t)ids[l] * KGD + tid];
    __syncthreads();

    float wb = entb[tid], wv = entv[tid];
    for (int l = 0; l < NCTX; l++) {
        float acc = 0.f;
#pragma unroll 8
        for (int dd = 0; dd < KGD; dd++)
            acc += rep[l][dd] * entW[dd * KGD + tid];
        float s = tanhf(acc + wb) * wv;
#pragma unroll
        for (int o = 16; o > 0; o >>= 1) s += __shfl_down_sync(0xffffffffu, s, o);
        if ((tid & 31) == 0) wsum[tid >> 5] = s;
        __syncthreads();
        if (tid == 0) ebuf[l] = wsum[0] + wsum[1] + wsum[2] + wsum[3];
        __syncthreads();
    }

    if (tid == 0) {
        float mx = -1e30f;
        for (int l = 0; l < NCTX; l++) {
            float v = (ids[l] != 0) ? ebuf[l] : -1e9f;
            ebuf[l] = v;
            mx = fmaxf(mx, v);
        }
        float sum = 0.f;
        for (int l = 0; l < NCTX; l++) { aw[l] = expf(ebuf[l] - mx); sum += aw[l]; }
        float inv = 1.0f / sum;
        for (int l = 0; l < NCTX; l++) aw[l] *= inv;
    }
    __syncthreads();

    float out = 0.f;
    for (int l = 0; l < NCTX; l++) out += aw[l] * rep[l][tid];
    g_ent_rep[b * KGD + tid] = out;
}

// ---------------- 5b: transpose tok_W, pre-rounded to tf32 -----------------
__global__ void transpose_kernel(const float* __restrict__ W) {
    __shared__ float t[32][33];
    int bx = blockIdx.x * 32, by = blockIdx.y * 32;
    int tx = threadIdx.x, ty = threadIdx.y;   // 32 x 8
#pragma unroll
    for (int i = 0; i < 32; i += 8)
        t[ty + i][tx] = W[(size_t)(by + ty + i) * TOKD + bx + tx];
    __syncthreads();
#pragma unroll
    for (int i = 0; i < 32; i += 8)
        g_Wt[(size_t)(bx + ty + i) * TOKD + by + tx] =
            __uint_as_float(f2tf32(t[tx][ty + i]));
}

// ---------------- 6: token attention logits via mma.sync tf32 --------------
#define KCH 16
#define NCHUNK (TOKD / KCH)   // 48
#define LDP 20                // smem row stride in floats (16 + 4 pad)

__device__ __forceinline__ void issue_chunk(const float* __restrict__ X,
                                            int row0, int col0, int c,
                                            float* Asm, float* Bsm, int tid) {
    int k0 = c * KCH;
#pragma unroll
    for (int i = 0; i < 2; i++) {
        int f = tid + i * 256;              // 0..511
        int rr = f >> 2;                    // 0..127
        int c4 = (f & 3) * 4;               // 0,4,8,12
        cp16(smem_u32(Asm + rr * LDP + c4),
             X + (size_t)(row0 + rr) * TOKD + k0 + c4);
        cp16(smem_u32(Bsm + rr * LDP + c4),
             g_Wt + (size_t)(col0 + rr) * TOKD + k0 + c4);
    }
    asm volatile("cp.async.commit_group;" ::: "memory");
}

__global__ void __launch_bounds__(256, 2)
tok_gemm_tc(const float* __restrict__ X,
            const float* __restrict__ tokb,
            const float* __restrict__ tokv) {
    __shared__ float As[2][128 * LDP];
    __shared__ float Bs[2][128 * LDP];

    int tid = threadIdx.x;
    int wid = tid >> 5, lane = tid & 31;
    int gid = lane >> 2, tig = lane & 3;
    int warpM = wid >> 1, warpN = wid & 1;
    int row0 = blockIdx.x * 128, col0 = blockIdx.y * 128;

    float acc[2][8][4];
#pragma unroll
    for (int mi = 0; mi < 2; mi++)
#pragma unroll
        for (int nj = 0; nj < 8; nj++)
#pragma unroll
            for (int q = 0; q < 4; q++) acc[mi][nj][q] = 0.f;

    issue_chunk(X, row0, col0, 0, As[0], Bs[0], tid);

    for (int c = 0; c < NCHUNK; c++) {
        if (c + 1 < NCHUNK) {
            issue_chunk(X, row0, col0, c + 1, As[(c + 1) & 1], Bs[(c + 1) & 1], tid);
            asm volatile("cp.async.wait_group 1;" ::: "memory");
        } else {
            asm volatile("cp.async.wait_group 0;" ::: "memory");
        }
        __syncthreads();

        const float* Ab = As[c & 1];
        const float* Bb = Bs[c & 1];
#pragma unroll
        for (int ks = 0; ks < 2; ks++) {
            int kk = ks * 8 + tig;
            uint32_t a[2][4];
#pragma unroll
            for (int mi = 0; mi < 2; mi++) {
                int rb = warpM * 32 + mi * 16 + gid;
                a[mi][0] = __float_as_uint(Ab[rb * LDP + kk]);
                a[mi][1] = __float_as_uint(Ab[(rb + 8) * LDP + kk]);
                a[mi][2] = __float_as_uint(Ab[rb * LDP + kk + 4]);
                a[mi][3] = __float_as_uint(Ab[(rb + 8) * LDP + kk + 4]);
            }
#pragma unroll
            for (int nj = 0; nj < 8; nj++) {
                int nb = warpN * 64 + nj * 8 + gid;
                uint32_t b0 = __float_as_uint(Bb[nb * LDP + kk]);
                uint32_t b1 = __float_as_uint(Bb[nb * LDP + kk + 4]);
                mma8(acc[0][nj], a[0], b0, b1);
                mma8(acc[1][nj], a[1], b0, b1);
            }
        }
        __syncthreads();
    }

    // epilogue
    float rsum[2][2] = {{0.f, 0.f}, {0.f, 0.f}};
#pragma unroll
    for (int mi = 0; mi < 2; mi++) {
#pragma unroll
        for (int nj = 0; nj < 8; nj++) {
            int n0 = col0 + warpN * 64 + nj * 8 + 2 * tig;
            float bb0 = __ldg(&tokb[n0]), bb1 = __ldg(&tokb[n0 + 1]);
            float vv0 = __ldg(&tokv[n0]), vv1 = __ldg(&tokv[n0 + 1]);
            rsum[mi][0] += tanhf(acc[mi][nj][0] + bb0) * vv0
                         + tanhf(acc[mi][nj][1] + bb1) * vv1;
            rsum[mi][1] += tanhf(acc[mi][nj][2] + bb0) * vv0
                         + tanhf(acc[mi][nj][3] + bb1) * vv1;
        }
    }
#pragma unroll
    for (int mi = 0; mi < 2; mi++)
#pragma unroll
        for (int h = 0; h < 2; h++) {
            float s = rsum[mi][h];
            s += __shfl_xor_sync(0xffffffffu, s, 1);
            s += __shfl_xor_sync(0xffffffffu, s, 2);
            if (tig == 0)
                atomicAdd(&g_e_tok[row0 + warpM * 32 + mi * 16 + h * 8 + gid], s);
        }
}

// ---------------- 7a: token masked softmax ---------------------------------
__global__ void tok_softmax_kernel(const int* __restrict__ ctx_tok) {
    int b = blockIdx.x;
    int tid = threadIdx.x;   // 0..255
    __shared__ float red[SEQL];

    float ev = g_e_tok[b * SEQL + tid];
    bool msk = (ctx_tok[b * SEQL + tid] != 0);
    float val = msk ? ev : -1e9f;

    red[tid] = val;
    __syncthreads();
    for (int s = 128; s > 0; s >>= 1) {
        if (tid < s) red[tid] = fmaxf(red[tid], red[tid + s]);
        __syncthreads();
    }
    float mx = red[0];
    __syncthreads();
    float ex = expf(val - mx);
    red[tid] = ex;
    __syncthreads();
    for (int s = 128; s > 0; s >>= 1) {
        if (tid < s) red[tid] += red[tid + s];
        __syncthreads();
    }
    g_a[b * SEQL + tid] = ex / red[0];
}

// ---------------- 7b: pool[b,d] = sum_l a[b,l] * X[b,l,d]  (192 CTAs) -------
__global__ void pool_kernel(const float* __restrict__ X) {
    int b = blockIdx.x;
    int dc = blockIdx.y;
    int tid = threadIdx.x;   // 0..127
    __shared__ float a[SEQL];
    for (int i = tid; i < SEQL; i += 128) a[i] = g_a[b * SEQL + i];
    __syncthreads();

    int d = dc * 128 + tid;
    const float* xp = X + (size_t)b * SEQL * TOKD + d;
    float s0 = 0.f, s1 = 0.f;
#pragma unroll 8
    for (int l = 0; l < SEQL; l += 2) {
        s0 += a[l] * xp[(size_t)l * TOKD];
        s1 += a[l + 1] * xp[(size_t)(l + 1) * TOKD];
    }
    g_pool[b * TOKD + d] = s0 + s1;
}

// ---------------- 7c: linear + gate + user ----------------------------------
__global__ void gate_kernel(const float* __restrict__ linW,
                            const float* __restrict__ linb,
                            const float* __restrict__ gateW,
                            const float* __restrict__ gateb) {
    int b = blockIdx.x;
    int tid = threadIdx.x;   // 0..127
    __shared__ float pool[TOKD];
    __shared__ float tokr[KGD];
    __shared__ float entr[KGD];

    for (int i = tid; i < TOKD; i += 128) pool[i] = g_pool[b * TOKD + i];
    __syncthreads();

    float s = linb[tid];
    const float* wp = linW + (size_t)tid * TOKD;
#pragma unroll 8
    for (int d = 0; d < TOKD; d++) s += pool[d] * wp[d];
    tokr[tid] = s;
    entr[tid] = g_ent_rep[b * KGD + tid];
    __syncthreads();

    float g = gateb[tid];
    const float* gw = gateW + (size_t)tid * (2 * KGD);
#pragma unroll 8
    for (int k = 0; k < KGD; k++) g += gw[k] * tokr[k];
#pragma unroll 8
    for (int k = 0; k < KGD; k++) g += gw[KGD + k] * entr[k];
    g = 1.0f / (1.0f + expf(-g));
    g_user[b * KGD + tid] = g * tokr[tid] + (1.0f - g) * entr[tid];
}

// ---------------- 8: scores = user @ kg^T -----------------------------------
__global__ void scores_kernel(float* __restrict__ out) {
    __shared__ float U[BATCH * KGD];
    int tid = threadIdx.x;
    for (int i = tid; i < BATCH * KGD; i += 256) U[i] = g_user[i];
    __syncthreads();

    int n = blockIdx.x * 256 + tid;
    if (n >= N_ENT) return;

    float acc[BATCH];
#pragma unroll
    for (int b = 0; b < BATCH; b++) acc[b] = 0.f;

    const float4* kgp = (const float4*)(g_kg + (size_t)n * KGD);
#pragma unroll 4
    for (int d4 = 0; d4 < KGD / 4; d4++) {
        float4 kv = kgp[d4];
#pragma unroll
        for (int b = 0; b < BATCH; b++) {
            float4 uv = *(const float4*)&U[b * KGD + d4 * 4];
            acc[b] += kv.x * uv.x + kv.y * uv.y + kv.z * uv.z + kv.w * uv.w;
        }
    }
#pragma unroll
    for (int b = 0; b < BATCH; b++) out[(size_t)b * N_ENT + n] = acc[b];
}

// ---------------- launch ----------------------------------------------------
extern "C" void kernel_launch(void* const* d_in, const int* in_sizes, int n_in,
                              void* d_out, int out_size) {
    const int*   ctx_ent  = (const int*)d_in[0];
    const int*   ctx_tok  = (const int*)d_in[1];
    const int*   edge_idx = (const int*)d_in[2];
    const int*   edge_typ = (const int*)d_in[3];
    const float* tok_emb  = (const float*)d_in[4];
    const float* comp     = (const float*)d_in[5];
    const float* basis    = (const float*)d_in[6];
    const float* root     = (const float*)d_in[7];
    const float* rg_bias  = (const float*)d_in[8];
    const float* entW     = (const float*)d_in[9];
    const float* entb     = (const float*)d_in[10];
    const float* entv     = (const float*)d_in[11];
    const float* tokW     = (const float*)d_in[12];
    const float* tokb     = (const float*)d_in[13];
    const float* tokv     = (const float*)d_in[14];
    const float* linW     = (const float*)d_in[15];
    const float* linb     = (const float*)d_in[16];
    const float* gateW    = (const float*)d_in[17];
    const float* gateb    = (const float*)d_in[18];
    float* out = (float*)d_out;

    zero_kernel<<<1024, 256>>>();
    weight_kernel<<<(960000 + 255) / 256, 256>>>(comp, basis);
    count_kernel<<<(NEDGE + 255) / 256, 256>>>(edge_idx, edge_typ);
    scan_kernel<<<1, 1024>>>();
    place_kernel<<<(NEDGE + 255) / 256, 256>>>(edge_idx, edge_typ);
    aggregate_kernel<<<(N_ENT * 32 + 255) / 256, 256>>>(root, rg_bias);
    ent_attn_kernel<<<BATCH, 128>>>(ctx_ent, entW, entb, entv);
    transpose_kernel<<<dim3(TOKD / 32, TOKD / 32), dim3(32, 8)>>>(tokW);
    tok_gemm_tc<<<dim3(64, 6), 256>>>(tok_emb, tokb, tokv);
    tok_softmax_kernel<<<BATCH, 256>>>(ctx_tok);
    pool_kernel<<<dim3(BATCH, 6), 128>>>(tok_emb);
    gate_kernel<<<BATCH, 128>>>(linW, linb, gateW, gateb);
    scores_kernel<<<(N_ENT + 255) / 256, 256>>>(out);
}

// round 7
// speedup vs baseline: 1.5841x; 1.1065x over previous
#include <cuda_runtime.h>
#include <cuda_bf16.h>
#include <cstdint>

#define N_ENT   30000
#define N_RELS  12
#define N_BASES 8
#define KGD     128
#define TOKD    768
#define BATCH   32
#define NCTX    50
#define SEQL    256
#define NEDGE   400000
#define MROWS   (BATCH * SEQL)   // 8192

// ---------------- scratch (__device__ globals; no allocations allowed) ----
__device__ __align__(256) __nv_bfloat16 g_wbf[N_RELS * N_ENT * KGD]; // 92 MB bf16 weights
__device__ float g_kg[N_ENT * KGD];                 // kg_embedding
__device__ int   g_cnt[N_RELS * N_ENT];             // per (rel,dst) edge counts
__device__ __align__(16) int g_deg[N_ENT];          // per-dst degree
__device__ __align__(16) int g_off[N_ENT + 4];      // exclusive scan of degree
__device__ int   g_pos[N_ENT];                      // running placement counters
__device__ uint32_t g_sorted[NEDGE];                // dst-bucketed (r<<16|src)
__device__ float g_e_part[12 * MROWS];              // token logit partials
__device__ float g_a[BATCH * SEQL];                 // token attention weights
__device__ float g_pool[BATCH * TOKD];              // pooled token rep
__device__ float g_ent_rep[BATCH * KGD];            // entity_attn_rep
__device__ float g_user[BATCH * KGD];               // user embedding
__device__ float g_Wt[TOKD * TOKD];                 // tok_W^T, pre-rounded to tf32

// ---------------- small PTX helpers ----------------------------------------
__device__ __forceinline__ uint32_t smem_u32(const void* p) {
    uint32_t a;
    asm("{ .reg .u64 t; cvta.to.shared.u64 t, %1; cvt.u32.u64 %0, t; }"
        : "=r"(a) : "l"(p));
    return a;
}

__device__ __forceinline__ void cp16(uint32_t s, const void* g) {
    asm volatile("cp.async.cg.shared.global [%0], [%1], 16;"
                 :: "r"(s), "l"(g) : "memory");
}

__device__ __forceinline__ uint32_t f2tf32(float f) {
    uint32_t r;
    asm("cvt.rna.tf32.f32 %0, %1;" : "=r"(r) : "f"(f));
    return r;
}

__device__ __forceinline__ void mma8(float* c, const uint32_t* a,
                                     uint32_t b0, uint32_t b1) {
    asm volatile(
        "mma.sync.aligned.m16n8k8.row.col.f32.tf32.tf32.f32 "
        "{%0,%1,%2,%3}, {%4,%5,%6,%7}, {%8,%9}, {%0,%1,%2,%3};"
        : "+f"(c[0]), "+f"(c[1]), "+f"(c[2]), "+f"(c[3])
        : "r"(a[0]), "r"(a[1]), "r"(a[2]), "r"(a[3]), "r"(b0), "r"(b1));
}

__device__ __forceinline__ uint32_t pack_bf16(float a, float b) {
    __nv_bfloat162 h = __floats2bfloat162_rn(a, b);
    return *(uint32_t*)&h;
}

// ---------------- 0: zero graph counters ----------------------------------
__global__ void zero_kernel() {
    int i = blockIdx.x * blockDim.x + threadIdx.x;
    int stride = gridDim.x * blockDim.x;
    for (int j = i; j < N_RELS * N_ENT; j += stride) g_cnt[j] = 0;
    for (int j = i; j < N_ENT; j += stride) { g_deg[j] = 0; g_pos[j] = 0; }
}

// ---------------- 1: wbf[r,n,d] = bf16( sum_b comp[r,b]*basis[b,n,d] ) ----
__global__ void weight_kernel(const float* __restrict__ comp,
                              const float* __restrict__ basis) {
    __shared__ float c[N_RELS * N_BASES];
    int tid = threadIdx.x;
    if (tid < N_RELS * N_BASES) c[tid] = comp[tid];
    __syncthreads();

    int i = blockIdx.x * blockDim.x + tid;
    const int NM4 = (N_ENT * KGD) / 4;       // 960000
    if (i >= NM4) return;

    float4 bv[N_BASES];
    const float4* b4 = (const float4*)basis;
#pragma unroll
    for (int b = 0; b < N_BASES; b++) bv[b] = b4[(size_t)b * NM4 + i];

#pragma unroll
    for (int r = 0; r < N_RELS; r++) {
        float4 o = make_float4(0.f, 0.f, 0.f, 0.f);
#pragma unroll
        for (int b = 0; b < N_BASES; b++) {
            float cc = c[r * N_BASES + b];
            o.x += cc * bv[b].x; o.y += cc * bv[b].y;
            o.z += cc * bv[b].z; o.w += cc * bv[b].w;
        }
        uint2 p = make_uint2(pack_bf16(o.x, o.y), pack_bf16(o.z, o.w));
        *((uint2*)(g_wbf + ((size_t)r * NM4 + i) * 4)) = p;
    }
}

// ---------------- 2: per-(rel,dst) counts + per-dst degree ----------------
__global__ void count_kernel(const int* __restrict__ edge_index,
                             const int* __restrict__ edge_type) {
    int e = blockIdx.x * blockDim.x + threadIdx.x;
    if (e >= NEDGE) return;
    int r = edge_type[e];
    int d = edge_index[NEDGE + e];
    atomicAdd(&g_cnt[r * N_ENT + d], 1);
    atomicAdd(&g_deg[d], 1);
}

// ---------------- 3a: exclusive scan of degree (single CTA, smem-staged) ---
#define SCAN_PER 30   // 1024 * 30 = 30720 >= 30000
__global__ void scan_kernel() {
    extern __shared__ int sdeg[];        // 30000 ints (117 KB, dynamic)
    __shared__ int part[1024];
    int t = threadIdx.x;

    // coalesced vectorized load g_deg -> smem
    for (int i = t; i < N_ENT / 4; i += 1024)
        ((int4*)sdeg)[i] = ((const int4*)g_deg)[i];
    __syncthreads();

    int base = t * SCAN_PER;
    int s = 0;
#pragma unroll
    for (int j = 0; j < SCAN_PER; j++) {
        int idx = base + j;
        if (idx < N_ENT) s += sdeg[idx];
    }
    part[t] = s;
    __syncthreads();
    for (int off = 1; off < 1024; off <<= 1) {
        int v = (t >= off) ? part[t - off] : 0;
        __syncthreads();
        part[t] += v;
        __syncthreads();
    }
    int run = part[t] - s;   // exclusive prefix
#pragma unroll
    for (int j = 0; j < SCAN_PER; j++) {
        int idx = base + j;
        if (idx < N_ENT) { int tmp = sdeg[idx]; sdeg[idx] = run; run += tmp; }
    }
    __syncthreads();

    // coalesced vectorized store smem -> g_off
    for (int i = t; i < N_ENT / 4; i += 1024)
        ((int4*)g_off)[i] = ((const int4*)sdeg)[i];
    if (t == 1023) g_off[N_ENT] = part[1023];
}

// ---------------- 3b: place edges into dst buckets --------------------------
__global__ void place_kernel(const int* __restrict__ edge_index,
                             const int* __restrict__ edge_type) {
    int e = blockIdx.x * blockDim.x + threadIdx.x;
    if (e >= NEDGE) return;
    int r = edge_type[e];
    int s = edge_index[e];
    int d = edge_index[NEDGE + e];
    int p = atomicAdd(&g_pos[d], 1);
    g_sorted[g_off[d] + p] = ((uint32_t)r << 16) | (uint32_t)s;
}

// ---------------- 3c: aggregate (1 warp per dst) + root + bias -------------
__global__ void aggregate_kernel(const float* __restrict__ root,
                                 const float* __restrict__ bias) {
    int w = (blockIdx.x * blockDim.x + threadIdx.x) >> 5;
    int lane = threadIdx.x & 31;
    if (w >= N_ENT) return;
    int d = w;
    int beg = g_off[d], end = g_off[d + 1];

    float a0 = 0.f, a1 = 0.f, a2 = 0.f, a3 = 0.f;
    for (int i = beg; i < end; i++) {
        uint32_t rec = __ldg(&g_sorted[i]);       // warp-uniform
        int r = rec >> 16, s = rec & 0xffff;
        int c = __ldg(&g_cnt[r * N_ENT + d]);     // warp-uniform
        float norm = 1.0f / (float)(c < 1 ? 1 : c);
        uint2 ww = *(const uint2*)(g_wbf + ((size_t)r * N_ENT + s) * KGD + lane * 4);
        a0 += __uint_as_float(ww.x << 16)          * norm;
        a1 += __uint_as_float(ww.x & 0xffff0000u)  * norm;
        a2 += __uint_as_float(ww.y << 16)          * norm;
        a3 += __uint_as_float(ww.y & 0xffff0000u)  * norm;
    }
    int o = d * KGD + lane * 4;
    float4 r4 = *(const float4*)(root + o);
    float4 b4 = *(const float4*)(bias + lane * 4);
    float4 outv = make_float4(a0 + r4.x + b4.x, a1 + r4.y + b4.y,
                              a2 + r4.z + b4.z, a3 + r4.w + b4.w);
    *(float4*)(g_kg + o) = outv;
}

// ---------------- 5: entity self-dot attention pool ------------------------
__global__ void ent_attn_kernel(const int* __restrict__ ctx_ent,
                                const float* __restrict__ entW,
                                const float* __restrict__ entb,
                                const float* __restrict__ entv) {
    int b = blockIdx.x;
    int tid = threadIdx.x;   // 0..127
    __shared__ float rep[NCTX][KGD];
    __shared__ float ebuf[NCTX];
    __shared__ float aw[NCTX];
    __shared__ int ids[NCTX];
    __shared__ float wsum[4];

    if (tid < NCTX) ids[tid] = ctx_ent[b * NCTX + tid];
    __syncthreads();
    for (int l = 0; l < NCTX; l++)
        rep[l][tid] = g_kg[(size_t)ids[l] * KGD + tid];
    __syncthreads();

    float wb = entb[tid], wv = entv[tid];
    for (int l = 0; l < NCTX; l++) {
        float acc = 0.f;
#pragma unroll 8
        for (int dd = 0; dd < KGD; dd++)
            acc += rep[l][dd] * entW[dd * KGD + tid];
        float s = tanhf(acc + wb) * wv;
#pragma unroll
        for (int o = 16; o > 0; o >>= 1) s += __shfl_down_sync(0xffffffffu, s, o);
        if ((tid & 31) == 0) wsum[tid >> 5] = s;
        __syncthreads();
        if (tid == 0) ebuf[l] = wsum[0] + wsum[1] + wsum[2] + wsum[3];
        __syncthreads();
    }

    if (tid == 0) {
        float mx = -1e30f;
        for (int l = 0; l < NCTX; l++) {
            float v = (ids[l] != 0) ? ebuf[l] : -1e9f;
            ebuf[l] = v;
            mx = fmaxf(mx, v);
        }
        float sum = 0.f;
        for (int l = 0; l < NCTX; l++) { aw[l] = expf(ebuf[l] - mx); sum += aw[l]; }
        float inv = 1.0f / sum;
        for (int l = 0; l < NCTX; l++) aw[l] *= inv;
    }
    __syncthreads();

    float out = 0.f;
    for (int l = 0; l < NCTX; l++) out += aw[l] * rep[l][tid];
    g_ent_rep[b * KGD + tid] = out;
}

// ---------------- 5b: transpose tok_W, pre-rounded to tf32 -----------------
__global__ void transpose_kernel(const float* __restrict__ W) {
    __shared__ float t[32][33];
    int bx = blockIdx.x * 32, by = blockIdx.y * 32;
    int tx = threadIdx.x, ty = threadIdx.y;   // 32 x 8
#pragma unroll
    for (int i = 0; i < 32; i += 8)
        t[ty + i][tx] = W[(size_t)(by + ty + i) * TOKD + bx + tx];
    __syncthreads();
#pragma unroll
    for (int i = 0; i < 32; i += 8)
        g_Wt[(size_t)(bx + ty + i) * TOKD + by + tx] =
            __uint_as_float(f2tf32(t[tx][ty + i]));
}

// ---------------- 6: token attention logits via mma.sync tf32 --------------
#define KCH 16
#define NCHUNK (TOKD / KCH)   // 48
#define LDP 20                // smem row stride in floats (16 + 4 pad)

__device__ __forceinline__ void issue_chunk(const float* __restrict__ X,
                                            int row0, int col0, int c,
                                            float* Asm, float* Bsm, int tid) {
    int k0 = c * KCH;
#pragma unroll
    for (int i = 0; i < 2; i++) {
        int f = tid + i * 256;              // 0..511
        int rr = f >> 2;                    // 0..127
        int c4 = (f & 3) * 4;               // 0,4,8,12
        cp16(smem_u32(Asm + rr * LDP + c4),
             X + (size_t)(row0 + rr) * TOKD + k0 + c4);
        cp16(smem_u32(Bsm + rr * LDP + c4),
             g_Wt + (size_t)(col0 + rr) * TOKD + k0 + c4);
    }
    asm volatile("cp.async.commit_group;" ::: "memory");
}

__global__ void __launch_bounds__(256, 2)
tok_gemm_tc(const float* __restrict__ X,
            const float* __restrict__ tokb,
            const float* __restrict__ tokv) {
    __shared__ float As[2][128 * LDP];
    __shared__ float Bs[2][128 * LDP];

    int tid = threadIdx.x;
    int wid = tid >> 5, lane = tid & 31;
    int gid = lane >> 2, tig = lane & 3;
    int warpM = wid >> 1, warpN = wid & 1;
    int row0 = blockIdx.x * 128, col0 = blockIdx.y * 128;

    float acc[2][8][4];
#pragma unroll
    for (int mi = 0; mi < 2; mi++)
#pragma unroll
        for (int nj = 0; nj < 8; nj++)
#pragma unroll
            for (int q = 0; q < 4; q++) acc[mi][nj][q] = 0.f;

    issue_chunk(X, row0, col0, 0, As[0], Bs[0], tid);

    for (int c = 0; c < NCHUNK; c++) {
        if (c + 1 < NCHUNK) {
            issue_chunk(X, row0, col0, c + 1, As[(c + 1) & 1], Bs[(c + 1) & 1], tid);
            asm volatile("cp.async.wait_group 1;" ::: "memory");
        } else {
            asm volatile("cp.async.wait_group 0;" ::: "memory");
        }
        __syncthreads();

        const float* Ab = As[c & 1];
        const float* Bb = Bs[c & 1];
#pragma unroll
        for (int ks = 0; ks < 2; ks++) {
            int kk = ks * 8 + tig;
            uint32_t a[2][4];
#pragma unroll
            for (int mi = 0; mi < 2; mi++) {
                int rb = warpM * 32 + mi * 16 + gid;
                a[mi][0] = __float_as_uint(Ab[rb * LDP + kk]);
                a[mi][1] = __float_as_uint(Ab[(rb + 8) * LDP + kk]);
                a[mi][2] = __float_as_uint(Ab[rb * LDP + kk + 4]);
                a[mi][3] = __float_as_uint(Ab[(rb + 8) * LDP + kk + 4]);
            }
#pragma unroll
            for (int nj = 0; nj < 8; nj++) {
                int nb = warpN * 64 + nj * 8 + gid;
                uint32_t b0 = __float_as_uint(Bb[nb * LDP + kk]);
                uint32_t b1 = __float_as_uint(Bb[nb * LDP + kk + 4]);
                mma8(acc[0][nj], a[0], b0, b1);
                mma8(acc[1][nj], a[1], b0, b1);
            }
        }
        __syncthreads();
    }

    // epilogue: per-(col-tile, warpN) partial row sums, no atomics
    float rsum[2][2] = {{0.f, 0.f}, {0.f, 0.f}};
#pragma unroll
    for (int mi = 0; mi < 2; mi++) {
#pragma unroll
        for (int nj = 0; nj < 8; nj++) {
            int n0 = col0 + warpN * 64 + nj * 8 + 2 * tig;
            float bb0 = __ldg(&tokb[n0]), bb1 = __ldg(&tokb[n0 + 1]);
            float vv0 = __ldg(&tokv[n0]), vv1 = __ldg(&tokv[n0 + 1]);
            rsum[mi][0] += tanhf(acc[mi][nj][0] + bb0) * vv0
                         + tanhf(acc[mi][nj][1] + bb1) * vv1;
            rsum[mi][1] += tanhf(acc[mi][nj][2] + bb0) * vv0
                         + tanhf(acc[mi][nj][3] + bb1) * vv1;
        }
    }
    int slot = blockIdx.y * 2 + warpN;   // 0..11
#pragma unroll
    for (int mi = 0; mi < 2; mi++)
#pragma unroll
        for (int h = 0; h < 2; h++) {
            float s = rsum[mi][h];
            s += __shfl_xor_sync(0xffffffffu, s, 1);
            s += __shfl_xor_sync(0xffffffffu, s, 2);
            if (tig == 0)
                g_e_part[slot * MROWS + row0 + warpM * 32 + mi * 16 + h * 8 + gid] = s;
        }
}

// ---------------- 7a: token masked softmax (sums 12 partials) --------------
__global__ void tok_softmax_kernel(const int* __restrict__ ctx_tok) {
    int b = blockIdx.x;
    int tid = threadIdx.x;   // 0..255
    __shared__ float red[SEQL];

    int row = b * SEQL + tid;
    float ev = 0.f;
#pragma unroll
    for (int j = 0; j < 12; j++) ev += g_e_part[j * MROWS + row];
    bool msk = (ctx_tok[row] != 0);
    float val = msk ? ev : -1e9f;

    red[tid] = val;
    __syncthreads();
    for (int s = 128; s > 0; s >>= 1) {
        if (tid < s) red[tid] = fmaxf(red[tid], red[tid + s]);
        __syncthreads();
    }
    float mx = red[0];
    __syncthreads();
    float ex = expf(val - mx);
    red[tid] = ex;
    __syncthreads();
    for (int s = 128; s > 0; s >>= 1) {
        if (tid < s) red[tid] += red[tid + s];
        __syncthreads();
    }
    g_a[row] = ex / red[0];
}

// ---------------- 7b: pool[b,d] = sum_l a[b,l] * X[b,l,d]  (192 CTAs) -------
__global__ void pool_kernel(const float* __restrict__ X) {
    int b = blockIdx.x;
    int dc = blockIdx.y;
    int tid = threadIdx.x;   // 0..127
    __shared__ float a[SEQL];
    for (int i = tid; i < SEQL; i += 128) a[i] = g_a[b * SEQL + i];
    __syncthreads();

    int d = dc * 128 + tid;
    const float* xp = X + (size_t)b * SEQL * TOKD + d;
    float s0 = 0.f, s1 = 0.f;
#pragma unroll 8
    for (int l = 0; l < SEQL; l += 2) {
        s0 += a[l] * xp[(size_t)l * TOKD];
        s1 += a[l + 1] * xp[(size_t)(l + 1) * TOKD];
    }
    g_pool[b * TOKD + d] = s0 + s1;
}

// ---------------- 7c: linear + gate + user ----------------------------------
__global__ void gate_kernel(const float* __restrict__ linW,
                            const float* __restrict__ linb,
                            const float* __restrict__ gateW,
                            const float* __restrict__ gateb) {
    int b = blockIdx.x;
    int tid = threadIdx.x;   // 0..127
    __shared__ float pool[TOKD];
    __shared__ float tokr[KGD];
    __shared__ float entr[KGD];

    for (int i = tid; i < TOKD; i += 128) pool[i] = g_pool[b * TOKD + i];
    __syncthreads();

    float s = linb[tid];
    const float* wp = linW + (size_t)tid * TOKD;
#pragma unroll 8
    for (int d = 0; d < TOKD; d++) s += pool[d] * wp[d];
    tokr[tid] = s;
    entr[tid] = g_ent_rep[b * KGD + tid];
    __syncthreads();

    float g = gateb[tid];
    const float* gw = gateW + (size_t)tid * (2 * KGD);
#pragma unroll 8
    for (int k = 0; k < KGD; k++) g += gw[k] * tokr[k];
#pragma unroll 8
    for (int k = 0; k < KGD; k++) g += gw[KGD + k] * entr[k];
    g = 1.0f / (1.0f + expf(-g));
    g_user[b * KGD + tid] = g * tokr[tid] + (1.0f - g) * entr[tid];
}

// ---------------- 8: scores = user @ kg^T -----------------------------------
__global__ void scores_kernel(float* __restrict__ out) {
    __shared__ float U[BATCH * KGD];
    int tid = threadIdx.x;
    for (int i = tid; i < BATCH * KGD; i += 256) U[i] = g_user[i];
    __syncthreads();

    int n = blockIdx.x * 256 + tid;
    if (n >= N_ENT) return;

    float acc[BATCH];
#pragma unroll
    for (int b = 0; b < BATCH; b++) acc[b] = 0.f;

    const float4* kgp = (const float4*)(g_kg + (size_t)n * KGD);
#pragma unroll 4
    for (int d4 = 0; d4 < KGD / 4; d4++) {
        float4 kv = kgp[d4];
#pragma unroll
        for (int b = 0; b < BATCH; b++) {
            float4 uv = *(const float4*)&U[b * KGD + d4 * 4];
            acc[b] += kv.x * uv.x + kv.y * uv.y + kv.z * uv.z + kv.w * uv.w;
        }
    }
#pragma unroll
    for (int b = 0; b < BATCH; b++) out[(size_t)b * N_ENT + n] = acc[b];
}

// ---------------- launch ----------------------------------------------------
extern "C" void kernel_launch(void* const* d_in, const int* in_sizes, int n_in,
                              void* d_out, int out_size) {
    const int*   ctx_ent  = (const int*)d_in[0];
    const int*   ctx_tok  = (const int*)d_in[1];
    const int*   edge_idx = (const int*)d_in[2];
    const int*   edge_typ = (const int*)d_in[3];
    const float* tok_emb  = (const float*)d_in[4];
    const float* comp     = (const float*)d_in[5];
    const float* basis    = (const float*)d_in[6];
    const float* root     = (const float*)d_in[7];
    const float* rg_bias  = (const float*)d_in[8];
    const float* entW     = (const float*)d_in[9];
    const float* entb     = (const float*)d_in[10];
    const float* entv     = (const float*)d_in[11];
    const float* tokW     = (const float*)d_in[12];
    const float* tokb     = (const float*)d_in[13];
    const float* tokv     = (const float*)d_in[14];
    const float* linW     = (const float*)d_in[15];
    const float* linb     = (const float*)d_in[16];
    const float* gateW    = (const float*)d_in[17];
    const float* gateb    = (const float*)d_in[18];
    float* out = (float*)d_out;

    cudaFuncSetAttribute(scan_kernel,
                         cudaFuncAttributeMaxDynamicSharedMemorySize,
                         N_ENT * (int)sizeof(int));

    cudaStream_t s1, s2;
    cudaEvent_t e0, ew, ep;
    cudaStreamCreateWithFlags(&s1, cudaStreamNonBlocking);
    cudaStreamCreateWithFlags(&s2, cudaStreamNonBlocking);
    cudaEventCreateWithFlags(&e0, cudaEventDisableTiming);
    cudaEventCreateWithFlags(&ew, cudaEventDisableTiming);
    cudaEventCreateWithFlags(&ep, cudaEventDisableTiming);

    // fork
    cudaEventRecord(e0, 0);
    cudaStreamWaitEvent(s1, e0, 0);
    cudaStreamWaitEvent(s2, e0, 0);

    // s1: RGCN weight table (memory-heavy, independent)
    weight_kernel<<<(960000 + 255) / 256, 256, 0, s1>>>(comp, basis);
    cudaEventRecord(ew, s1);

    // s2: full token path (independent of RGCN until gate)
    transpose_kernel<<<dim3(TOKD / 32, TOKD / 32), dim3(32, 8), 0, s2>>>(tokW);
    tok_gemm_tc<<<dim3(64, 6), 256, 0, s2>>>(tok_emb, tokb, tokv);
    tok_softmax_kernel<<<BATCH, 256, 0, s2>>>(ctx_tok);
    pool_kernel<<<dim3(BATCH, 6), 128, 0, s2>>>(tok_emb);
    cudaEventRecord(ep, s2);

    // main: graph bookkeeping
    zero_kernel<<<512, 256>>>();
    count_kernel<<<(NEDGE + 255) / 256, 256>>>(edge_idx, edge_typ);
    scan_kernel<<<1, 1024, N_ENT * sizeof(int)>>>();
    place_kernel<<<(NEDGE + 255) / 256, 256>>>(edge_idx, edge_typ);

    // join weight -> aggregate
    cudaStreamWaitEvent(0, ew, 0);
    aggregate_kernel<<<(N_ENT * 32 + 255) / 256, 256>>>(root, rg_bias);
    ent_attn_kernel<<<BATCH, 128>>>(ctx_ent, entW, entb, entv);

    // join token path -> gate, scores
    cudaStreamWaitEvent(0, ep, 0);
    gate_kernel<<<BATCH, 128>>>(linW, linb, gateW, gateb);
    scores_kernel<<<(N_ENT + 255) / 256, 256>>>(out);

    cudaEventDestroy(e0);
    cudaEventDestroy(ew);
    cudaEventDestroy(ep);
    cudaStreamDestroy(s1);
    cudaStreamDestroy(s2);
}

// round 8
// speedup vs baseline: 1.7133x; 1.0816x over previous
#include <cuda_runtime.h>
#include <cuda_bf16.h>
#include <cuda_fp16.h>
#include <cstdint>

#define N_ENT   30000
#define N_RELS  12
#define N_BASES 8
#define KGD     128
#define TOKD    768
#define BATCH   32
#define NCTX    50
#define SEQL    256
#define NEDGE   400000
#define MROWS   (BATCH * SEQL)   // 8192

// ---------------- scratch (__device__ globals; no allocations allowed) ----
__device__ __align__(256) __nv_bfloat16 g_wbf[N_RELS * N_ENT * KGD]; // 92 MB bf16 weights
__device__ float g_kg[N_ENT * KGD];                 // kg_embedding
__device__ int   g_cnt[N_RELS * N_ENT];             // per (rel,dst) edge counts
__device__ __align__(16) int g_deg[N_ENT];          // per-dst degree
__device__ __align__(16) int g_off[N_ENT + 4];      // exclusive scan of degree
__device__ int   g_pos[N_ENT];                      // running placement counters
__device__ uint32_t g_sorted[NEDGE];                // dst-bucketed (r<<16|src)
__device__ float g_e_part[12 * MROWS];              // token logit partials
__device__ float g_a[BATCH * SEQL];                 // token attention weights
__device__ float g_pool[BATCH * TOKD];              // pooled token rep
__device__ float g_ent_rep[BATCH * KGD];            // entity_attn_rep
__device__ float g_user[BATCH * KGD];               // user embedding
__device__ __align__(16) __half g_Xh[MROWS * TOKD]; // token_embedding in fp16
__device__ __align__(16) __half g_Wth[TOKD * TOKD]; // tok_W^T in fp16

// ---------------- small PTX helpers ----------------------------------------
__device__ __forceinline__ uint32_t smem_u32(const void* p) {
    uint32_t a;
    asm("{ .reg .u64 t; cvta.to.shared.u64 t, %1; cvt.u32.u64 %0, t; }"
        : "=r"(a) : "l"(p));
    return a;
}

__device__ __forceinline__ void cp16(uint32_t s, const void* g) {
    asm volatile("cp.async.cg.shared.global [%0], [%1], 16;"
                 :: "r"(s), "l"(g) : "memory");
}

__device__ __forceinline__ void mma16(float* c, const uint32_t* a,
                                      uint32_t b0, uint32_t b1) {
    asm volatile(
        "mma.sync.aligned.m16n8k16.row.col.f32.f16.f16.f32 "
        "{%0,%1,%2,%3}, {%4,%5,%6,%7}, {%8,%9}, {%0,%1,%2,%3};"
        : "+f"(c[0]), "+f"(c[1]), "+f"(c[2]), "+f"(c[3])
        : "r"(a[0]), "r"(a[1]), "r"(a[2]), "r"(a[3]), "r"(b0), "r"(b1));
}

__device__ __forceinline__ uint32_t pack_bf16(float a, float b) {
    __nv_bfloat162 h = __floats2bfloat162_rn(a, b);
    return *(uint32_t*)&h;
}

// ---------------- 0: zero graph counters ----------------------------------
__global__ void zero_kernel() {
    int i = blockIdx.x * blockDim.x + threadIdx.x;
    int stride = gridDim.x * blockDim.x;
    for (int j = i; j < N_RELS * N_ENT; j += stride) g_cnt[j] = 0;
    for (int j = i; j < N_ENT; j += stride) { g_deg[j] = 0; g_pos[j] = 0; }
}

// ---------------- 1: wbf[r,n,d] = bf16( sum_b comp[r,b]*basis[b,n,d] ) ----
__global__ void weight_kernel(const float* __restrict__ comp,
                              const float* __restrict__ basis) {
    __shared__ float c[N_RELS * N_BASES];
    int tid = threadIdx.x;
    if (tid < N_RELS * N_BASES) c[tid] = comp[tid];
    __syncthreads();

    int i = blockIdx.x * blockDim.x + tid;
    const int NM4 = (N_ENT * KGD) / 4;       // 960000
    if (i >= NM4) return;

    float4 bv[N_BASES];
    const float4* b4 = (const float4*)basis;
#pragma unroll
    for (int b = 0; b < N_BASES; b++) bv[b] = b4[(size_t)b * NM4 + i];

#pragma unroll
    for (int r = 0; r < N_RELS; r++) {
        float4 o = make_float4(0.f, 0.f, 0.f, 0.f);
#pragma unroll
        for (int b = 0; b < N_BASES; b++) {
            float cc = c[r * N_BASES + b];
            o.x += cc * bv[b].x; o.y += cc * bv[b].y;
            o.z += cc * bv[b].z; o.w += cc * bv[b].w;
        }
        uint2 p = make_uint2(pack_bf16(o.x, o.y), pack_bf16(o.z, o.w));
        *((uint2*)(g_wbf + ((size_t)r * NM4 + i) * 4)) = p;
    }
}

// ---------------- 2: per-(rel,dst) counts + per-dst degree ----------------
__global__ void count_kernel(const int* __restrict__ edge_index,
                             const int* __restrict__ edge_type) {
    int e = blockIdx.x * blockDim.x + threadIdx.x;
    if (e >= NEDGE) return;
    int r = edge_type[e];
    int d = edge_index[NEDGE + e];
    atomicAdd(&g_cnt[r * N_ENT + d], 1);
    atomicAdd(&g_deg[d], 1);
}

// ---------------- 3a: exclusive scan of degree (single CTA, smem-staged) ---
#define SCAN_PER 30   // 1024 * 30 = 30720 >= 30000
__global__ void scan_kernel() {
    extern __shared__ int sdeg[];        // 30000 ints (dynamic)
    __shared__ int part[1024];
    int t = threadIdx.x;

    for (int i = t; i < N_ENT / 4; i += 1024)
        ((int4*)sdeg)[i] = ((const int4*)g_deg)[i];
    __syncthreads();

    int base = t * SCAN_PER;
    int s = 0;
#pragma unroll
    for (int j = 0; j < SCAN_PER; j++) {
        int idx = base + j;
        if (idx < N_ENT) s += sdeg[idx];
    }
    part[t] = s;
    __syncthreads();
    for (int off = 1; off < 1024; off <<= 1) {
        int v = (t >= off) ? part[t - off] : 0;
        __syncthreads();
        part[t] += v;
        __syncthreads();
    }
    int run = part[t] - s;   // exclusive prefix
#pragma unroll
    for (int j = 0; j < SCAN_PER; j++) {
        int idx = base + j;
        if (idx < N_ENT) { int tmp = sdeg[idx]; sdeg[idx] = run; run += tmp; }
    }
    __syncthreads();

    for (int i = t; i < N_ENT / 4; i += 1024)
        ((int4*)g_off)[i] = ((const int4*)sdeg)[i];
    if (t == 1023) g_off[N_ENT] = part[1023];
}

// ---------------- 3b: place edges into dst buckets --------------------------
__global__ void place_kernel(const int* __restrict__ edge_index,
                             const int* __restrict__ edge_type) {
    int e = blockIdx.x * blockDim.x + threadIdx.x;
    if (e >= NEDGE) return;
    int r = edge_type[e];
    int s = edge_index[e];
    int d = edge_index[NEDGE + e];
    int p = atomicAdd(&g_pos[d], 1);
    g_sorted[g_off[d] + p] = ((uint32_t)r << 16) | (uint32_t)s;
}

// ---------------- 3c: aggregate (1 warp per dst) + root + bias -------------
__global__ void aggregate_kernel(const float* __restrict__ root,
                                 const float* __restrict__ bias) {
    int w = (blockIdx.x * blockDim.x + threadIdx.x) >> 5;
    int lane = threadIdx.x & 31;
    if (w >= N_ENT) return;
    int d = w;
    int beg = g_off[d], end = g_off[d + 1];

    float a0 = 0.f, a1 = 0.f, a2 = 0.f, a3 = 0.f;
    for (int i = beg; i < end; i++) {
        uint32_t rec = __ldg(&g_sorted[i]);       // warp-uniform
        int r = rec >> 16, s = rec & 0xffff;
        int c = __ldg(&g_cnt[r * N_ENT + d]);     // warp-uniform
        float norm = 1.0f / (float)(c < 1 ? 1 : c);
        uint2 ww = *(const uint2*)(g_wbf + ((size_t)r * N_ENT + s) * KGD + lane * 4);
        a0 += __uint_as_float(ww.x << 16)          * norm;
        a1 += __uint_as_float(ww.x & 0xffff0000u)  * norm;
        a2 += __uint_as_float(ww.y << 16)          * norm;
        a3 += __uint_as_float(ww.y & 0xffff0000u)  * norm;
    }
    int o = d * KGD + lane * 4;
    float4 r4 = *(const float4*)(root + o);
    float4 b4 = *(const float4*)(bias + lane * 4);
    float4 outv = make_float4(a0 + r4.x + b4.x, a1 + r4.y + b4.y,
                              a2 + r4.z + b4.z, a3 + r4.w + b4.w);
    *(float4*)(g_kg + o) = outv;
}

// ---------------- 5: entity self-dot attention pool ------------------------
__global__ void ent_attn_kernel(const int* __restrict__ ctx_ent,
                                const float* __restrict__ entW,
                                const float* __restrict__ entb,
                                const float* __restrict__ entv) {
    int b = blockIdx.x;
    int tid = threadIdx.x;   // 0..127
    __shared__ float rep[NCTX][KGD];
    __shared__ float ebuf[NCTX];
    __shared__ float aw[NCTX];
    __shared__ int ids[NCTX];
    __shared__ float wsum[4];

    if (tid < NCTX) ids[tid] = ctx_ent[b * NCTX + tid];
    __syncthreads();
    for (int l = 0; l < NCTX; l++)
        rep[l][tid] = g_kg[(size_t)ids[l] * KGD + tid];
    __syncthreads();

    float wb = entb[tid], wv = entv[tid];
    for (int l = 0; l < NCTX; l++) {
        float acc = 0.f;
#pragma unroll 8
        for (int dd = 0; dd < KGD; dd++)
            acc += rep[l][dd] * entW[dd * KGD + tid];
        float s = tanhf(acc + wb) * wv;
#pragma unroll
        for (int o = 16; o > 0; o >>= 1) s += __shfl_down_sync(0xffffffffu, s, o);
        if ((tid & 31) == 0) wsum[tid >> 5] = s;
        __syncthreads();
        if (tid == 0) ebuf[l] = wsum[0] + wsum[1] + wsum[2] + wsum[3];
        __syncthreads();
    }

    if (tid == 0) {
        float mx = -1e30f;
        for (int l = 0; l < NCTX; l++) {
            float v = (ids[l] != 0) ? ebuf[l] : -1e9f;
            ebuf[l] = v;
            mx = fmaxf(mx, v);
        }
        float sum = 0.f;
        for (int l = 0; l < NCTX; l++) { aw[l] = expf(ebuf[l] - mx); sum += aw[l]; }
        float inv = 1.0f / sum;
        for (int l = 0; l < NCTX; l++) aw[l] *= inv;
    }
    __syncthreads();

    float out = 0.f;
    for (int l = 0; l < NCTX; l++) out += aw[l] * rep[l][tid];
    g_ent_rep[b * KGD + tid] = out;
}

// ---------------- 5a: convert token embedding to fp16 ----------------------
__global__ void xcvt_kernel(const float* __restrict__ X) {
    int i = blockIdx.x * blockDim.x + threadIdx.x;   // float4 index
    const int N4 = MROWS * TOKD / 4;                  // 1572864
    if (i >= N4) return;
    float4 v = ((const float4*)X)[i];
    __half2 h0 = __floats2half2_rn(v.x, v.y);
    __half2 h1 = __floats2half2_rn(v.z, v.w);
    uint2 p = make_uint2(*(uint32_t*)&h0, *(uint32_t*)&h1);
    ((uint2*)g_Xh)[i] = p;
}

// ---------------- 5b: transpose tok_W into fp16 K-major B ------------------
__global__ void transpose_kernel(const float* __restrict__ W) {
    __shared__ float t[32][33];
    int bx = blockIdx.x * 32, by = blockIdx.y * 32;
    int tx = threadIdx.x, ty = threadIdx.y;   // 32 x 8
#pragma unroll
    for (int i = 0; i < 32; i += 8)
        t[ty + i][tx] = W[(size_t)(by + ty + i) * TOKD + bx + tx];
    __syncthreads();
#pragma unroll
    for (int i = 0; i < 32; i += 8)
        g_Wth[(size_t)(bx + ty + i) * TOKD + by + tx] = __float2half(t[tx][ty + i]);
}

// ---------------- 6: token attention logits via mma.sync fp16 --------------
#define KCH 32
#define NCHUNK (TOKD / KCH)   // 24
#define LDH 40                // smem row stride in halves (32 + 8 pad = 80B)

__device__ __forceinline__ void issue_chunk(int row0, int col0, int c,
                                            __half* Asm, __half* Bsm, int tid) {
    int k0 = c * KCH;
#pragma unroll
    for (int i = 0; i < 2; i++) {
        int f = tid + i * 256;              // 0..511
        int rr = f >> 2;                    // 0..127
        int seg = (f & 3) * 8;              // 0,8,16,24 halves
        cp16(smem_u32(Asm + rr * LDH + seg),
             g_Xh + (size_t)(row0 + rr) * TOKD + k0 + seg);
        cp16(smem_u32(Bsm + rr * LDH + seg),
             g_Wth + (size_t)(col0 + rr) * TOKD + k0 + seg);
    }
    asm volatile("cp.async.commit_group;" ::: "memory");
}

__global__ void __launch_bounds__(256, 2)
tok_gemm_fp16(const float* __restrict__ tokb,
              const float* __restrict__ tokv) {
    __shared__ __half As[2][128 * LDH];
    __shared__ __half Bs[2][128 * LDH];

    int tid = threadIdx.x;
    int wid = tid >> 5, lane = tid & 31;
    int gid = lane >> 2, tig = lane & 3;
    int warpM = wid >> 1, warpN = wid & 1;
    int row0 = blockIdx.x * 128, col0 = blockIdx.y * 128;

    float acc[2][8][4];
#pragma unroll
    for (int mi = 0; mi < 2; mi++)
#pragma unroll
        for (int nj = 0; nj < 8; nj++)
#pragma unroll
            for (int q = 0; q < 4; q++) acc[mi][nj][q] = 0.f;

    issue_chunk(row0, col0, 0, As[0], Bs[0], tid);

    for (int c = 0; c < NCHUNK; c++) {
        if (c + 1 < NCHUNK) {
            issue_chunk(row0, col0, c + 1, As[(c + 1) & 1], Bs[(c + 1) & 1], tid);
            asm volatile("cp.async.wait_group 1;" ::: "memory");
        } else {
            asm volatile("cp.async.wait_group 0;" ::: "memory");
        }
        __syncthreads();

        const __half* Ab = As[c & 1];
        const __half* Bb = Bs[c & 1];
#pragma unroll
        for (int ks = 0; ks < 2; ks++) {
            int kh = ks * 16 + 2 * tig;
            uint32_t a[2][4];
#pragma unroll
            for (int mi = 0; mi < 2; mi++) {
                int rb = warpM * 32 + mi * 16 + gid;
                a[mi][0] = *(const uint32_t*)(Ab + rb * LDH + kh);
                a[mi][1] = *(const uint32_t*)(Ab + (rb + 8) * LDH + kh);
                a[mi][2] = *(const uint32_t*)(Ab + rb * LDH + kh + 8);
                a[mi][3] = *(const uint32_t*)(Ab + (rb + 8) * LDH + kh + 8);
            }
#pragma unroll
            for (int nj = 0; nj < 8; nj++) {
                int nb = warpN * 64 + nj * 8 + gid;
                uint32_t b0 = *(const uint32_t*)(Bb + nb * LDH + kh);
                uint32_t b1 = *(const uint32_t*)(Bb + nb * LDH + kh + 8);
                mma16(acc[0][nj], a[0], b0, b1);
                mma16(acc[1][nj], a[1], b0, b1);
            }
        }
        __syncthreads();
    }

    // epilogue: per-(col-tile, warpN) partial row sums, no atomics
    float rsum[2][2] = {{0.f, 0.f}, {0.f, 0.f}};
#pragma unroll
    for (int mi = 0; mi < 2; mi++) {
#pragma unroll
        for (int nj = 0; nj < 8; nj++) {
            int n0 = col0 + warpN * 64 + nj * 8 + 2 * tig;
            float bb0 = __ldg(&tokb[n0]), bb1 = __ldg(&tokb[n0 + 1]);
            float vv0 = __ldg(&tokv[n0]), vv1 = __ldg(&tokv[n0 + 1]);
            rsum[mi][0] += tanhf(acc[mi][nj][0] + bb0) * vv0
                         + tanhf(acc[mi][nj][1] + bb1) * vv1;
            rsum[mi][1] += tanhf(acc[mi][nj][2] + bb0) * vv0
                         + tanhf(acc[mi][nj][3] + bb1) * vv1;
        }
    }
    int slot = blockIdx.y * 2 + warpN;   // 0..11
#pragma unroll
    for (int mi = 0; mi < 2; mi++)
#pragma unroll
        for (int h = 0; h < 2; h++) {
            float s = rsum[mi][h];
            s += __shfl_xor_sync(0xffffffffu, s, 1);
            s += __shfl_xor_sync(0xffffffffu, s, 2);
            if (tig == 0)
                g_e_part[slot * MROWS + row0 + warpM * 32 + mi * 16 + h * 8 + gid] = s;
        }
}

// ---------------- 7a: token masked softmax (sums 12 partials) --------------
__global__ void tok_softmax_kernel(const int* __restrict__ ctx_tok) {
    int b = blockIdx.x;
    int tid = threadIdx.x;   // 0..255
    __shared__ float red[SEQL];

    int row = b * SEQL + tid;
    float ev = 0.f;
#pragma unroll
    for (int j = 0; j < 12; j++) ev += g_e_part[j * MROWS + row];
    bool msk = (ctx_tok[row] != 0);
    float val = msk ? ev : -1e9f;

    red[tid] = val;
    __syncthreads();
    for (int s = 128; s > 0; s >>= 1) {
        if (tid < s) red[tid] = fmaxf(red[tid], red[tid + s]);
        __syncthreads();
    }
    float mx = red[0];
    __syncthreads();
    float ex = expf(val - mx);
    red[tid] = ex;
    __syncthreads();
    for (int s = 128; s > 0; s >>= 1) {
        if (tid < s) red[tid] += red[tid + s];
        __syncthreads();
    }
    g_a[row] = ex / red[0];
}

// ---------------- 7b: pool[b,d] = sum_l a[b,l] * X[b,l,d]  (192 CTAs) -------
__global__ void pool_kernel(const float* __restrict__ X) {
    int b = blockIdx.x;
    int dc = blockIdx.y;
    int tid = threadIdx.x;   // 0..127
    __shared__ float a[SEQL];
    for (int i = tid; i < SEQL; i += 128) a[i] = g_a[b * SEQL + i];
    __syncthreads();

    int d = dc * 128 + tid;
    const float* xp = X + (size_t)b * SEQL * TOKD + d;
    float s0 = 0.f, s1 = 0.f, s2 = 0.f, s3 = 0.f;
#pragma unroll 4
    for (int l = 0; l < SEQL; l += 4) {
        s0 += a[l] * xp[(size_t)l * TOKD];
        s1 += a[l + 1] * xp[(size_t)(l + 1) * TOKD];
        s2 += a[l + 2] * xp[(size_t)(l + 2) * TOKD];
        s3 += a[l + 3] * xp[(size_t)(l + 3) * TOKD];
    }
    g_pool[b * TOKD + d] = (s0 + s1) + (s2 + s3);
}

// ---------------- 7c: linear + gate + user ----------------------------------
__global__ void gate_kernel(const float* __restrict__ linW,
                            const float* __restrict__ linb,
                            const float* __restrict__ gateW,
                            const float* __restrict__ gateb) {
    int b = blockIdx.x;
    int tid = threadIdx.x;   // 0..127
    __shared__ float pool[TOKD];
    __shared__ float tokr[KGD];
    __shared__ float entr[KGD];

    for (int i = tid; i < TOKD; i += 128) pool[i] = g_pool[b * TOKD + i];
    __syncthreads();

    float s = linb[tid];
    const float* wp = linW + (size_t)tid * TOKD;
#pragma unroll 8
    for (int d = 0; d < TOKD; d++) s += pool[d] * wp[d];
    tokr[tid] = s;
    entr[tid] = g_ent_rep[b * KGD + tid];
    __syncthreads();

    float g = gateb[tid];
    const float* gw = gateW + (size_t)tid * (2 * KGD);
#pragma unroll 8
    for (int k = 0; k < KGD; k++) g += gw[k] * tokr[k];
#pragma unroll 8
    for (int k = 0; k < KGD; k++) g += gw[KGD + k] * entr[k];
    g = 1.0f / (1.0f + expf(-g));
    g_user[b * KGD + tid] = g * tokr[tid] + (1.0f - g) * entr[tid];
}

// ---------------- 8: scores = user @ kg^T -----------------------------------
__global__ void scores_kernel(float* __restrict__ out) {
    __shared__ float U[BATCH * KGD];
    int tid = threadIdx.x;
    for (int i = tid; i < BATCH * KGD; i += 256) U[i] = g_user[i];
    __syncthreads();

    int n = blockIdx.x * 256 + tid;
    if (n >= N_ENT) return;

    float acc[BATCH];
#pragma unroll
    for (int b = 0; b < BATCH; b++) acc[b] = 0.f;

    const float4* kgp = (const float4*)(g_kg + (size_t)n * KGD);
#pragma unroll 4
    for (int d4 = 0; d4 < KGD / 4; d4++) {
        float4 kv = kgp[d4];
#pragma unroll
        for (int b = 0; b < BATCH; b++) {
            float4 uv = *(const float4*)&U[b * KGD + d4 * 4];
            acc[b] += kv.x * uv.x + kv.y * uv.y + kv.z * uv.z + kv.w * uv.w;
        }
    }
#pragma unroll
    for (int b = 0; b < BATCH; b++) out[(size_t)b * N_ENT + n] = acc[b];
}

// ---------------- launch ----------------------------------------------------
extern "C" void kernel_launch(void* const* d_in, const int* in_sizes, int n_in,
                              void* d_out, int out_size) {
    const int*   ctx_ent  = (const int*)d_in[0];
    const int*   ctx_tok  = (const int*)d_in[1];
    const int*   edge_idx = (const int*)d_in[2];
    const int*   edge_typ = (const int*)d_in[3];
    const float* tok_emb  = (const float*)d_in[4];
    const float* comp     = (const float*)d_in[5];
    const float* basis    = (const float*)d_in[6];
    const float* root     = (const float*)d_in[7];
    const float* rg_bias  = (const float*)d_in[8];
    const float* entW     = (const float*)d_in[9];
    const float* entb     = (const float*)d_in[10];
    const float* entv     = (const float*)d_in[11];
    const float* tokW     = (const float*)d_in[12];
    const float* tokb     = (const float*)d_in[13];
    const float* tokv     = (const float*)d_in[14];
    const float* linW     = (const float*)d_in[15];
    const float* linb     = (const float*)d_in[16];
    const float* gateW    = (const float*)d_in[17];
    const float* gateb    = (const float*)d_in[18];
    float* out = (float*)d_out;

    cudaFuncSetAttribute(scan_kernel,
                         cudaFuncAttributeMaxDynamicSharedMemorySize,
                         N_ENT * (int)sizeof(int));

    cudaStream_t s1, s2;
    cudaEvent_t e0, ew, ep;
    cudaStreamCreateWithFlags(&s1, cudaStreamNonBlocking);
    cudaStreamCreateWithFlags(&s2, cudaStreamNonBlocking);
    cudaEventCreateWithFlags(&e0, cudaEventDisableTiming);
    cudaEventCreateWithFlags(&ew, cudaEventDisableTiming);
    cudaEventCreateWithFlags(&ep, cudaEventDisableTiming);

    // fork
    cudaEventRecord(e0, 0);
    cudaStreamWaitEvent(s1, e0, 0);
    cudaStreamWaitEvent(s2, e0, 0);

    // s1: RGCN weight table (launch #1)
    weight_kernel<<<(960000 + 255) / 256, 256, 0, s1>>>(comp, basis);
    cudaEventRecord(ew, s1);

    // s2: token path — gemm is submission #4 for ncu visibility
    xcvt_kernel<<<(MROWS * TOKD / 4 + 255) / 256, 256, 0, s2>>>(tok_emb);   // #2
    transpose_kernel<<<dim3(TOKD / 32, TOKD / 32), dim3(32, 8), 0, s2>>>(tokW); // #3
    tok_gemm_fp16<<<dim3(64, 6), 256, 0, s2>>>(tokb, tokv);                 // #4
    tok_softmax_kernel<<<BATCH, 256, 0, s2>>>(ctx_tok);
    pool_kernel<<<dim3(BATCH, 6), 128, 0, s2>>>(tok_emb);
    cudaEventRecord(ep, s2);

    // main: graph bookkeeping
    zero_kernel<<<512, 256>>>();
    count_kernel<<<(NEDGE + 255) / 256, 256>>>(edge_idx, edge_typ);
    scan_kernel<<<1, 1024, N_ENT * sizeof(int)>>>();
    place_kernel<<<(NEDGE + 255) / 256, 256>>>(edge_idx, edge_typ);

    // join weight -> aggregate
    cudaStreamWaitEvent(0, ew, 0);
    aggregate_kernel<<<(N_ENT * 32 + 255) / 256, 256>>>(root, rg_bias);
    ent_attn_kernel<<<BATCH, 128>>>(ctx_ent, entW, entb, entv);

    // join token path -> gate, scores
    cudaStreamWaitEvent(0, ep, 0);
    gate_kernel<<<BATCH, 128>>>(linW, linb, gateW, gateb);
    scores_kernel<<<(N_ENT + 255) / 256, 256>>>(out);

    cudaEventDestroy(e0);
    cudaEventDestroy(ew);
    cudaEventDestroy(ep);
    cudaStreamDestroy(s1);
    cudaStreamDestroy(s2);
}